// round 1
// baseline (speedup 1.0000x reference)
#include <cuda_runtime.h>

// Problem constants
#define D_IN   1024
#define NSEQ   2048
#define BATCH  4
#define NHEAD  16
#define HDIM   64
#define MTOT   (BATCH*NSEQ)   // 8192

// Scratch (no cudaMalloc allowed)
__device__ float g_Q[(size_t)MTOT * D_IN];
__device__ float g_K[(size_t)MTOT * D_IN];
__device__ float g_V[(size_t)MTOT * D_IN];
__device__ float g_C[(size_t)MTOT * D_IN];

// ---------------------------------------------------------------------------
// Tiled SGEMM: C[M,N] = A[M,K] @ B[K,N] (+ bias). BM=128 BN=64 BK=16,
// 256 threads, 8x4 per-thread microtile. M%128==0, N%64==0, K%16==0 assumed.
// ---------------------------------------------------------------------------
__global__ __launch_bounds__(256) void sgemm_kernel(
    const float* __restrict__ A, const float* __restrict__ B,
    const float* __restrict__ bias, float* __restrict__ C,
    int M, int N, int K)
{
    const int BM = 128, BN = 64, BK = 16;
    __shared__ float As[BK][BM];   // transposed A tile
    __shared__ float Bs[BK][BN];

    const int tid = threadIdx.x;
    const int tx = tid & 15;       // 0..15 -> 4 cols each
    const int ty = tid >> 4;       // 0..15 -> 8 rows each
    const int rowBase = blockIdx.y * BM;
    const int colBase = blockIdx.x * BN;

    float acc[8][4];
    #pragma unroll
    for (int i = 0; i < 8; i++)
        #pragma unroll
        for (int j = 0; j < 4; j++) acc[i][j] = 0.f;

    for (int k0 = 0; k0 < K; k0 += BK) {
        // Load A tile: 128x16 = 512 float4, 2 per thread, store transposed
        #pragma unroll
        for (int i = 0; i < 2; i++) {
            int f = tid + i * 256;
            int r = f >> 2, c4 = f & 3;
            float4 v = *(const float4*)(A + (size_t)(rowBase + r) * K + k0 + c4 * 4);
            As[c4 * 4 + 0][r] = v.x;
            As[c4 * 4 + 1][r] = v.y;
            As[c4 * 4 + 2][r] = v.z;
            As[c4 * 4 + 3][r] = v.w;
        }
        // Load B tile: 16x64 = 256 float4, 1 per thread
        {
            int r = tid >> 4, c4 = tid & 15;
            *(float4*)&Bs[r][c4 * 4] =
                *(const float4*)(B + (size_t)(k0 + r) * N + colBase + c4 * 4);
        }
        __syncthreads();

        #pragma unroll
        for (int k = 0; k < BK; k++) {
            float4 a0 = *(float4*)&As[k][ty * 8];
            float4 a1 = *(float4*)&As[k][ty * 8 + 4];
            float4 b0 = *(float4*)&Bs[k][tx * 4];
            float a[8] = {a0.x, a0.y, a0.z, a0.w, a1.x, a1.y, a1.z, a1.w};
            float bb[4] = {b0.x, b0.y, b0.z, b0.w};
            #pragma unroll
            for (int i = 0; i < 8; i++)
                #pragma unroll
                for (int j = 0; j < 4; j++)
                    acc[i][j] += a[i] * bb[j];
        }
        __syncthreads();
    }

    const int c = colBase + tx * 4;
    float4 bz = make_float4(0.f, 0.f, 0.f, 0.f);
    if (bias) bz = *(const float4*)(bias + c);
    #pragma unroll
    for (int i = 0; i < 8; i++) {
        int r = rowBase + ty * 8 + i;
        float4 o;
        o.x = acc[i][0] + bz.x;
        o.y = acc[i][1] + bz.y;
        o.z = acc[i][2] + bz.z;
        o.w = acc[i][3] + bz.w;
        *(float4*)(C + (size_t)r * N + c) = o;
    }
}

// ---------------------------------------------------------------------------
// Causal flash attention, fp32. One thread per query row, 128 rows/CTA,
// 64-key tiles, online softmax. Q scaled by 1/sqrt(64) at load.
// grid = (NSEQ/128, NHEAD, BATCH), 128 threads, dynamic smem.
// ---------------------------------------------------------------------------
#define ABM 128
#define ABN 64
#define APAD 68   // row stride in floats: conflict-free, 16B-aligned
#define ATTN_SMEM ((ABM*APAD + 2*ABN*APAD) * 4)

__global__ __launch_bounds__(128) void attn_kernel(
    const float* __restrict__ Q, const float* __restrict__ Kg,
    const float* __restrict__ Vg, float* __restrict__ Ctx)
{
    extern __shared__ float sm[];
    float* Qs = sm;                     // ABM x APAD
    float* Ks = sm + ABM * APAD;        // ABN x APAD
    float* Vs = Ks + ABN * APAD;        // ABN x APAD

    const int tid = threadIdx.x;
    const int q0 = blockIdx.x * ABM;
    const int h = blockIdx.y, b = blockIdx.z;
    const size_t baseQ = ((size_t)(b * NSEQ + q0)) * D_IN + h * HDIM;

    // Load+scale Q tile: 128x64 = 2048 float4, coalesced
    #pragma unroll
    for (int j = 0; j < 16; j++) {
        int f = tid + j * 128;
        int r = f >> 4, c4 = f & 15;
        float4 v = *(const float4*)(Q + baseQ + (size_t)r * D_IN + c4 * 4);
        v.x *= 0.125f; v.y *= 0.125f; v.z *= 0.125f; v.w *= 0.125f;
        *(float4*)&Qs[r * APAD + c4 * 4] = v;
    }

    float Oc[HDIM];
    #pragma unroll
    for (int d = 0; d < HDIM; d++) Oc[d] = 0.f;
    float m = -1e30f, l = 0.f;
    const int qrow = q0 + tid;
    const int ktmax = (q0 + ABM - 1) / ABN;

    for (int kt = 0; kt <= ktmax; kt++) {
        __syncthreads();
        const size_t baseK = ((size_t)(b * NSEQ + kt * ABN)) * D_IN + h * HDIM;
        #pragma unroll
        for (int j = 0; j < 8; j++) {
            int f = tid + j * 128;
            int r = f >> 4, c4 = f & 15;
            *(float4*)&Ks[r * APAD + c4 * 4] =
                *(const float4*)(Kg + baseK + (size_t)r * D_IN + c4 * 4);
            *(float4*)&Vs[r * APAD + c4 * 4] =
                *(const float4*)(Vg + baseK + (size_t)r * D_IN + c4 * 4);
        }
        __syncthreads();

        if (kt * ABN <= qrow) {  // tile has at least one unmasked key for this row
            float s[ABN];
            #pragma unroll
            for (int c = 0; c < ABN; c++) s[c] = 0.f;

            #pragma unroll 1
            for (int k4 = 0; k4 < HDIM / 4; k4++) {
                float4 q4 = *(float4*)&Qs[tid * APAD + k4 * 4];
                #pragma unroll
                for (int c = 0; c < ABN; c++) {
                    float4 kv = *(float4*)&Ks[c * APAD + k4 * 4];
                    s[c] += q4.x * kv.x + q4.y * kv.y + q4.z * kv.z + q4.w * kv.w;
                }
            }

            const bool tmask = (kt * ABN + ABN - 1) > qrow;
            float mn = m;
            #pragma unroll
            for (int c = 0; c < ABN; c++) {
                if (tmask && (kt * ABN + c) > qrow) s[c] = -1e30f;
                mn = fmaxf(mn, s[c]);
            }
            float corr = __expf(m - mn);
            l *= corr;
            #pragma unroll
            for (int d = 0; d < HDIM; d++) Oc[d] *= corr;

            #pragma unroll 1
            for (int c = 0; c < ABN; c++) {
                float p = __expf(s[c] - mn);
                l += p;
                #pragma unroll
                for (int d4 = 0; d4 < HDIM / 4; d4++) {
                    float4 vv = *(float4*)&Vs[c * APAD + d4 * 4];
                    Oc[d4 * 4 + 0] += p * vv.x;
                    Oc[d4 * 4 + 1] += p * vv.y;
                    Oc[d4 * 4 + 2] += p * vv.z;
                    Oc[d4 * 4 + 3] += p * vv.w;
                }
            }
            m = mn;
        }
    }

    // Stage output through smem for coalesced store
    __syncthreads();
    float inv = 1.f / l;
    #pragma unroll
    for (int d = 0; d < HDIM; d++) Qs[tid * APAD + d] = Oc[d] * inv;
    __syncthreads();
    #pragma unroll
    for (int j = 0; j < 16; j++) {
        int f = tid + j * 128;
        int r = f >> 4, c4 = f & 15;
        *(float4*)(Ctx + baseQ + (size_t)r * D_IN + c4 * 4) =
            *(float4*)&Qs[r * APAD + c4 * 4];
    }
}

// ---------------------------------------------------------------------------
extern "C" void kernel_launch(void* const* d_in, const int* in_sizes, int n_in,
                              void* d_out, int out_size)
{
    const float* X  = (const float*)d_in[0];
    const float* Wq = (const float*)d_in[1];
    const float* Wk = (const float*)d_in[2];
    const float* Wv = (const float*)d_in[3];
    const float* Wo = (const float*)d_in[4];
    const float* bo = (const float*)d_in[5];
    float* out = (float*)d_out;

    float *pQ, *pK, *pV, *pC;
    cudaGetSymbolAddress((void**)&pQ, g_Q);
    cudaGetSymbolAddress((void**)&pK, g_K);
    cudaGetSymbolAddress((void**)&pV, g_V);
    cudaGetSymbolAddress((void**)&pC, g_C);

    dim3 gg(D_IN / 64, MTOT / 128);  // (16, 64)

    sgemm_kernel<<<gg, 256>>>(X, Wq, nullptr, pQ, MTOT, D_IN, D_IN);
    sgemm_kernel<<<gg, 256>>>(X, Wk, nullptr, pK, MTOT, D_IN, D_IN);
    sgemm_kernel<<<gg, 256>>>(X, Wv, nullptr, pV, MTOT, D_IN, D_IN);

    cudaFuncSetAttribute(attn_kernel,
                         cudaFuncAttributeMaxDynamicSharedMemorySize, ATTN_SMEM);
    attn_kernel<<<dim3(NSEQ / ABM, NHEAD, BATCH), 128, ATTN_SMEM>>>(pQ, pK, pV, pC);

    sgemm_kernel<<<gg, 256>>>(pC, Wo, bo, out, MTOT, D_IN, D_IN);
}

// round 3
// speedup vs baseline: 1.2738x; 1.2738x over previous
#include <cuda_runtime.h>
#include <cuda_bf16.h>
#include <cstdint>

// Problem constants
#define D_IN   1024
#define NSEQ   2048
#define BATCH  4
#define NHEAD  16
#define HDIM   64
#define MTOT   (BATCH*NSEQ)   // 8192
#define GK     1024

// ---------------------------------------------------------------------------
// Scratch (no cudaMalloc allowed)
// ---------------------------------------------------------------------------
__device__ float g_Q[(size_t)MTOT * D_IN];
__device__ float g_K[(size_t)MTOT * D_IN];
__device__ float g_V[(size_t)MTOT * D_IN];
__device__ float g_C[(size_t)MTOT * D_IN];
__device__ __nv_bfloat16 g_Xh[(size_t)MTOT * D_IN];   // split activations (hi)
__device__ __nv_bfloat16 g_Xl[(size_t)MTOT * D_IN];   // split activations (lo)
__device__ __nv_bfloat16 g_Wth[(size_t)D_IN * D_IN];  // transposed weight (hi)
__device__ __nv_bfloat16 g_Wtl[(size_t)D_IN * D_IN];  // transposed weight (lo)

// ---------------------------------------------------------------------------
// Split fp32 -> bf16 hi + bf16 lo (elementwise, 4 per thread)
// ---------------------------------------------------------------------------
__global__ __launch_bounds__(256) void split_kernel(
    const float* __restrict__ x, __nv_bfloat16* __restrict__ hi,
    __nv_bfloat16* __restrict__ lo)
{
    size_t i = (size_t)blockIdx.x * 256 + threadIdx.x;
    float4 v = ((const float4*)x)[i];
    __nv_bfloat16 h0 = __float2bfloat16(v.x), h1 = __float2bfloat16(v.y);
    __nv_bfloat16 h2 = __float2bfloat16(v.z), h3 = __float2bfloat16(v.w);
    __nv_bfloat16 l0 = __float2bfloat16(v.x - __bfloat162float(h0));
    __nv_bfloat16 l1 = __float2bfloat16(v.y - __bfloat162float(h1));
    __nv_bfloat16 l2 = __float2bfloat16(v.z - __bfloat162float(h2));
    __nv_bfloat16 l3 = __float2bfloat16(v.w - __bfloat162float(h3));
    __nv_bfloat162 hv0{h0, h1}, hv1{h2, h3}, lv0{l0, l1}, lv1{l2, l3};
    ((__nv_bfloat162*)hi)[i * 2 + 0] = hv0;
    ((__nv_bfloat162*)hi)[i * 2 + 1] = hv1;
    ((__nv_bfloat162*)lo)[i * 2 + 0] = lv0;
    ((__nv_bfloat162*)lo)[i * 2 + 1] = lv1;
}

// ---------------------------------------------------------------------------
// Transpose + split: W[K,N] fp32 -> Wt[N,K] bf16 hi/lo. 32x32 tiles.
// ---------------------------------------------------------------------------
__global__ __launch_bounds__(256) void transpose_split_kernel(
    const float* __restrict__ W, __nv_bfloat16* __restrict__ Th,
    __nv_bfloat16* __restrict__ Tl)
{
    __shared__ float t[32][33];
    int x0 = blockIdx.x * 32, y0 = blockIdx.y * 32;
    int tx = threadIdx.x, ty = threadIdx.y;  // blockDim (32, 8)
    #pragma unroll
    for (int j = 0; j < 32; j += 8)
        t[ty + j][tx] = W[(size_t)(y0 + ty + j) * D_IN + x0 + tx];
    __syncthreads();
    #pragma unroll
    for (int j = 0; j < 32; j += 8) {
        float v = t[tx][ty + j];
        __nv_bfloat16 h = __float2bfloat16(v);
        Th[(size_t)(x0 + ty + j) * D_IN + y0 + tx] = h;
        Tl[(size_t)(x0 + ty + j) * D_IN + y0 + tx] = __float2bfloat16(v - __bfloat162float(h));
    }
}

// ---------------------------------------------------------------------------
// mma.sync helper (bf16 -> f32, m16n8k16, row.col)
// ---------------------------------------------------------------------------
__device__ __forceinline__ void mma_bf16(float* c, const uint32_t* a,
                                         uint32_t b0, uint32_t b1)
{
    asm volatile(
        "mma.sync.aligned.m16n8k16.row.col.f32.bf16.bf16.f32 "
        "{%0,%1,%2,%3}, {%4,%5,%6,%7}, {%8,%9}, {%0,%1,%2,%3};"
        : "+f"(c[0]), "+f"(c[1]), "+f"(c[2]), "+f"(c[3])
        : "r"(a[0]), "r"(a[1]), "r"(a[2]), "r"(a[3]), "r"(b0), "r"(b1));
}

// ---------------------------------------------------------------------------
// Split-bf16 tensor-core GEMM: C[M,1024] = A[M,1024] @ Bt[1024,1024]^T (+bias)
// A hi/lo bf16 [M,K] K-major; Bt hi/lo bf16 [N,K] K-major.
// CTA tile 128x128, 8 warps (4 rows x 2 cols) of 32x64, BK=16.
// grid = (N/128, M/128), 256 threads.
// ---------------------------------------------------------------------------
#define BK 16
#define ASTR 24   // smem row stride in bf16 (48B): g*12+tig mod 32 is a permutation

__global__ __launch_bounds__(256) void gemm_mma_kernel(
    const __nv_bfloat16* __restrict__ Ah, const __nv_bfloat16* __restrict__ Al,
    const __nv_bfloat16* __restrict__ Bh, const __nv_bfloat16* __restrict__ Bl,
    const float* __restrict__ bias, float* __restrict__ C)
{
    __shared__ __nv_bfloat16 sAh[128 * ASTR];
    __shared__ __nv_bfloat16 sAl[128 * ASTR];
    __shared__ __nv_bfloat16 sBh[128 * ASTR];
    __shared__ __nv_bfloat16 sBl[128 * ASTR];

    const int tid = threadIdx.x;
    const int wid = tid >> 5, lane = tid & 31;
    const int g = lane >> 2, tig = lane & 3;
    const int warpRow = (wid >> 1) * 32;   // 0,32,64,96
    const int warpCol = (wid & 1) * 64;    // 0,64
    const int rowBase = blockIdx.y * 128;
    const int colBase = blockIdx.x * 128;

    const __nv_bfloat16* gA0 = Ah + (size_t)rowBase * GK;
    const __nv_bfloat16* gA1 = Al + (size_t)rowBase * GK;
    const __nv_bfloat16* gB0 = Bh + (size_t)colBase * GK;
    const __nv_bfloat16* gB1 = Bl + (size_t)colBase * GK;

    float acc[2][8][4];
    #pragma unroll
    for (int mt = 0; mt < 2; mt++)
        #pragma unroll
        for (int nt = 0; nt < 8; nt++)
            #pragma unroll
            for (int j = 0; j < 4; j++) acc[mt][nt][j] = 0.f;

    // load indices: thread t -> row t/2, 8-bf16 half t%2
    const int lr = tid >> 1, lh = tid & 1;
    const size_t goff = (size_t)lr * GK + lh * 8;
    const int soff = lr * ASTR + lh * 8;

    for (int k0 = 0; k0 < GK; k0 += BK) {
        __syncthreads();
        *(uint4*)(sAh + soff) = *(const uint4*)(gA0 + goff + k0);
        *(uint4*)(sAl + soff) = *(const uint4*)(gA1 + goff + k0);
        *(uint4*)(sBh + soff) = *(const uint4*)(gB0 + goff + k0);
        *(uint4*)(sBl + soff) = *(const uint4*)(gB1 + goff + k0);
        __syncthreads();

        // A fragments (2 m-tiles, hi+lo)
        uint32_t ah[2][4], al[2][4];
        #pragma unroll
        for (int mt = 0; mt < 2; mt++) {
            const int r0 = warpRow + mt * 16 + g;
            ah[mt][0] = *(const uint32_t*)(sAh + r0 * ASTR + tig * 2);
            ah[mt][1] = *(const uint32_t*)(sAh + (r0 + 8) * ASTR + tig * 2);
            ah[mt][2] = *(const uint32_t*)(sAh + r0 * ASTR + tig * 2 + 8);
            ah[mt][3] = *(const uint32_t*)(sAh + (r0 + 8) * ASTR + tig * 2 + 8);
            al[mt][0] = *(const uint32_t*)(sAl + r0 * ASTR + tig * 2);
            al[mt][1] = *(const uint32_t*)(sAl + (r0 + 8) * ASTR + tig * 2);
            al[mt][2] = *(const uint32_t*)(sAl + r0 * ASTR + tig * 2 + 8);
            al[mt][3] = *(const uint32_t*)(sAl + (r0 + 8) * ASTR + tig * 2 + 8);
        }

        #pragma unroll
        for (int nt = 0; nt < 8; nt++) {
            const int n0 = warpCol + nt * 8 + g;
            uint32_t b0h = *(const uint32_t*)(sBh + n0 * ASTR + tig * 2);
            uint32_t b1h = *(const uint32_t*)(sBh + n0 * ASTR + tig * 2 + 8);
            uint32_t b0l = *(const uint32_t*)(sBl + n0 * ASTR + tig * 2);
            uint32_t b1l = *(const uint32_t*)(sBl + n0 * ASTR + tig * 2 + 8);
            #pragma unroll
            for (int mt = 0; mt < 2; mt++) {
                mma_bf16(acc[mt][nt], ah[mt], b0h, b1h);
                mma_bf16(acc[mt][nt], ah[mt], b0l, b1l);
                mma_bf16(acc[mt][nt], al[mt], b0h, b1h);
            }
        }
    }

    // epilogue
    #pragma unroll
    for (int mt = 0; mt < 2; mt++) {
        #pragma unroll
        for (int nt = 0; nt < 8; nt++) {
            const int col = colBase + warpCol + nt * 8 + tig * 2;
            const int r0 = rowBase + warpRow + mt * 16 + g;
            float bx = 0.f, by = 0.f;
            if (bias) { bx = bias[col]; by = bias[col + 1]; }
            float2 v0 = {acc[mt][nt][0] + bx, acc[mt][nt][1] + by};
            float2 v1 = {acc[mt][nt][2] + bx, acc[mt][nt][3] + by};
            *(float2*)(C + (size_t)r0 * D_IN + col) = v0;
            *(float2*)(C + (size_t)(r0 + 8) * D_IN + col) = v1;
        }
    }
}

// ---------------------------------------------------------------------------
// Causal flash attention, fp32 (unchanged from R1 — passing, ~1.8ms).
// ---------------------------------------------------------------------------
#define ABM 128
#define ABN 64
#define APAD 68
#define ATTN_SMEM ((ABM*APAD + 2*ABN*APAD) * 4)

__global__ __launch_bounds__(128) void attn_kernel(
    const float* __restrict__ Q, const float* __restrict__ Kg,
    const float* __restrict__ Vg, float* __restrict__ Ctx)
{
    extern __shared__ float smf[];
    float* Qs = smf;
    float* Ks = smf + ABM * APAD;
    float* Vs = Ks + ABN * APAD;

    const int tid = threadIdx.x;
    const int q0 = blockIdx.x * ABM;
    const int h = blockIdx.y, b = blockIdx.z;
    const size_t baseQ = ((size_t)(b * NSEQ + q0)) * D_IN + h * HDIM;

    #pragma unroll
    for (int j = 0; j < 16; j++) {
        int f = tid + j * 128;
        int r = f >> 4, c4 = f & 15;
        float4 v = *(const float4*)(Q + baseQ + (size_t)r * D_IN + c4 * 4);
        v.x *= 0.125f; v.y *= 0.125f; v.z *= 0.125f; v.w *= 0.125f;
        *(float4*)&Qs[r * APAD + c4 * 4] = v;
    }

    float Oc[HDIM];
    #pragma unroll
    for (int d = 0; d < HDIM; d++) Oc[d] = 0.f;
    float m = -1e30f, l = 0.f;
    const int qrow = q0 + tid;
    const int ktmax = (q0 + ABM - 1) / ABN;

    for (int kt = 0; kt <= ktmax; kt++) {
        __syncthreads();
        const size_t baseK = ((size_t)(b * NSEQ + kt * ABN)) * D_IN + h * HDIM;
        #pragma unroll
        for (int j = 0; j < 8; j++) {
            int f = tid + j * 128;
            int r = f >> 4, c4 = f & 15;
            *(float4*)&Ks[r * APAD + c4 * 4] =
                *(const float4*)(Kg + baseK + (size_t)r * D_IN + c4 * 4);
            *(float4*)&Vs[r * APAD + c4 * 4] =
                *(const float4*)(Vg + baseK + (size_t)r * D_IN + c4 * 4);
        }
        __syncthreads();

        if (kt * ABN <= qrow) {
            float s[ABN];
            #pragma unroll
            for (int c = 0; c < ABN; c++) s[c] = 0.f;

            #pragma unroll 1
            for (int k4 = 0; k4 < HDIM / 4; k4++) {
                float4 q4 = *(float4*)&Qs[tid * APAD + k4 * 4];
                #pragma unroll
                for (int c = 0; c < ABN; c++) {
                    float4 kv = *(float4*)&Ks[c * APAD + k4 * 4];
                    s[c] += q4.x * kv.x + q4.y * kv.y + q4.z * kv.z + q4.w * kv.w;
                }
            }

            const bool tmask = (kt * ABN + ABN - 1) > qrow;
            float mn = m;
            #pragma unroll
            for (int c = 0; c < ABN; c++) {
                if (tmask && (kt * ABN + c) > qrow) s[c] = -1e30f;
                mn = fmaxf(mn, s[c]);
            }
            float corr = __expf(m - mn);
            l *= corr;
            #pragma unroll
            for (int d = 0; d < HDIM; d++) Oc[d] *= corr;

            #pragma unroll 1
            for (int c = 0; c < ABN; c++) {
                float p = __expf(s[c] - mn);
                l += p;
                #pragma unroll
                for (int d4 = 0; d4 < HDIM / 4; d4++) {
                    float4 vv = *(float4*)&Vs[c * APAD + d4 * 4];
                    Oc[d4 * 4 + 0] += p * vv.x;
                    Oc[d4 * 4 + 1] += p * vv.y;
                    Oc[d4 * 4 + 2] += p * vv.z;
                    Oc[d4 * 4 + 3] += p * vv.w;
                }
            }
            m = mn;
        }
    }

    __syncthreads();
    float inv = 1.f / l;
    #pragma unroll
    for (int d = 0; d < HDIM; d++) Qs[tid * APAD + d] = Oc[d] * inv;
    __syncthreads();
    #pragma unroll
    for (int j = 0; j < 16; j++) {
        int f = tid + j * 128;
        int r = f >> 4, c4 = f & 15;
        *(float4*)(Ctx + baseQ + (size_t)r * D_IN + c4 * 4) =
            *(float4*)&Qs[r * APAD + c4 * 4];
    }
}

// ---------------------------------------------------------------------------
extern "C" void kernel_launch(void* const* d_in, const int* in_sizes, int n_in,
                              void* d_out, int out_size)
{
    const float* X  = (const float*)d_in[0];
    const float* Wq = (const float*)d_in[1];
    const float* Wk = (const float*)d_in[2];
    const float* Wv = (const float*)d_in[3];
    const float* Wo = (const float*)d_in[4];
    const float* bo = (const float*)d_in[5];
    float* out = (float*)d_out;

    float *pQ, *pK, *pV, *pC;
    __nv_bfloat16 *pXh, *pXl, *pWth, *pWtl;
    cudaGetSymbolAddress((void**)&pQ, g_Q);
    cudaGetSymbolAddress((void**)&pK, g_K);
    cudaGetSymbolAddress((void**)&pV, g_V);
    cudaGetSymbolAddress((void**)&pC, g_C);
    cudaGetSymbolAddress((void**)&pXh, g_Xh);
    cudaGetSymbolAddress((void**)&pXl, g_Xl);
    cudaGetSymbolAddress((void**)&pWth, g_Wth);
    cudaGetSymbolAddress((void**)&pWtl, g_Wtl);

    static bool attrs_set = false;
    if (!attrs_set) {
        cudaFuncSetAttribute(attn_kernel,
                             cudaFuncAttributeMaxDynamicSharedMemorySize, ATTN_SMEM);
        attrs_set = true;
    }

    const int splitBlocks = (MTOT * D_IN) / (256 * 4);   // 8192
    const dim3 trGrid(D_IN / 32, D_IN / 32), trBlk(32, 8);
    const dim3 gemmGrid(D_IN / 128, MTOT / 128);          // (8, 64)

    // X -> bf16 hi/lo
    split_kernel<<<splitBlocks, 256>>>(X, pXh, pXl);

    // Q, K, V projections
    transpose_split_kernel<<<trGrid, trBlk>>>(Wq, pWth, pWtl);
    gemm_mma_kernel<<<gemmGrid, 256>>>(pXh, pXl, pWth, pWtl, nullptr, pQ);
    transpose_split_kernel<<<trGrid, trBlk>>>(Wk, pWth, pWtl);
    gemm_mma_kernel<<<gemmGrid, 256>>>(pXh, pXl, pWth, pWtl, nullptr, pK);
    transpose_split_kernel<<<trGrid, trBlk>>>(Wv, pWth, pWtl);
    gemm_mma_kernel<<<gemmGrid, 256>>>(pXh, pXl, pWth, pWtl, nullptr, pV);

    // attention
    attn_kernel<<<dim3(NSEQ / ABM, NHEAD, BATCH), 128, ATTN_SMEM>>>(pQ, pK, pV, pC);

    // ctx -> bf16 hi/lo (reuse X buffers), output projection + bias
    split_kernel<<<splitBlocks, 256>>>(pC, pXh, pXl);
    transpose_split_kernel<<<trGrid, trBlk>>>(Wo, pWth, pWtl);
    gemm_mma_kernel<<<gemmGrid, 256>>>(pXh, pXl, pWth, pWtl, bo, out);
}

// round 5
// speedup vs baseline: 2.5848x; 2.0291x over previous
#include <cuda_runtime.h>
#include <cuda_bf16.h>
#include <cstdint>

// Problem constants
#define D_IN   1024
#define NSEQ   2048
#define BATCH  4
#define NHEAD  16
#define HDIM   64
#define MTOT   (BATCH*NSEQ)   // 8192
#define GK     1024

// ---------------------------------------------------------------------------
// Scratch (no cudaMalloc allowed)
// ---------------------------------------------------------------------------
__device__ float g_Q[(size_t)MTOT * D_IN];
__device__ float g_K[(size_t)MTOT * D_IN];
__device__ float g_V[(size_t)MTOT * D_IN];
__device__ float g_C[(size_t)MTOT * D_IN];
__device__ __nv_bfloat16 g_Xh[(size_t)MTOT * D_IN];
__device__ __nv_bfloat16 g_Xl[(size_t)MTOT * D_IN];
__device__ __nv_bfloat16 g_Wth[(size_t)D_IN * D_IN];
__device__ __nv_bfloat16 g_Wtl[(size_t)D_IN * D_IN];
// attention operands
__device__ __nv_bfloat16 g_Qh[(size_t)MTOT * D_IN];
__device__ __nv_bfloat16 g_Ql[(size_t)MTOT * D_IN];
__device__ __nv_bfloat16 g_Kh[(size_t)MTOT * D_IN];
__device__ __nv_bfloat16 g_Kl[(size_t)MTOT * D_IN];
__device__ __nv_bfloat16 g_Vth[(size_t)BATCH * NHEAD * HDIM * NSEQ];
__device__ __nv_bfloat16 g_Vtl[(size_t)BATCH * NHEAD * HDIM * NSEQ];

// fast exp2 via MUFU
__device__ __forceinline__ float fexp2(float x) {
    float r;
    asm("ex2.approx.f32 %0, %1;" : "=f"(r) : "f"(x));
    return r;
}

// ---------------------------------------------------------------------------
// Split fp32 -> bf16 hi + lo
// ---------------------------------------------------------------------------
__global__ __launch_bounds__(256) void split_kernel(
    const float* __restrict__ x, __nv_bfloat16* __restrict__ hi,
    __nv_bfloat16* __restrict__ lo)
{
    size_t i = (size_t)blockIdx.x * 256 + threadIdx.x;
    float4 v = ((const float4*)x)[i];
    __nv_bfloat16 h0 = __float2bfloat16(v.x), h1 = __float2bfloat16(v.y);
    __nv_bfloat16 h2 = __float2bfloat16(v.z), h3 = __float2bfloat16(v.w);
    __nv_bfloat16 l0 = __float2bfloat16(v.x - __bfloat162float(h0));
    __nv_bfloat16 l1 = __float2bfloat16(v.y - __bfloat162float(h1));
    __nv_bfloat16 l2 = __float2bfloat16(v.z - __bfloat162float(h2));
    __nv_bfloat16 l3 = __float2bfloat16(v.w - __bfloat162float(h3));
    __nv_bfloat162 hv0{h0, h1}, hv1{h2, h3}, lv0{l0, l1}, lv1{l2, l3};
    ((__nv_bfloat162*)hi)[i * 2 + 0] = hv0;
    ((__nv_bfloat162*)hi)[i * 2 + 1] = hv1;
    ((__nv_bfloat162*)lo)[i * 2 + 0] = lv0;
    ((__nv_bfloat162*)lo)[i * 2 + 1] = lv1;
}

// ---------------------------------------------------------------------------
// Transpose + split weights: W[K,N] fp32 -> Wt[N,K] bf16 hi/lo
// ---------------------------------------------------------------------------
__global__ __launch_bounds__(256) void transpose_split_kernel(
    const float* __restrict__ W, __nv_bfloat16* __restrict__ Th,
    __nv_bfloat16* __restrict__ Tl)
{
    __shared__ float t[32][33];
    int x0 = blockIdx.x * 32, y0 = blockIdx.y * 32;
    int tx = threadIdx.x, ty = threadIdx.y;  // (32, 8)
    #pragma unroll
    for (int j = 0; j < 32; j += 8)
        t[ty + j][tx] = W[(size_t)(y0 + ty + j) * D_IN + x0 + tx];
    __syncthreads();
    #pragma unroll
    for (int j = 0; j < 32; j += 8) {
        float v = t[tx][ty + j];
        __nv_bfloat16 h = __float2bfloat16(v);
        Th[(size_t)(x0 + ty + j) * D_IN + y0 + tx] = h;
        Tl[(size_t)(x0 + ty + j) * D_IN + y0 + tx] = __float2bfloat16(v - __bfloat162float(h));
    }
}

// ---------------------------------------------------------------------------
// Per-head V transpose+split: V[b*2048+key][h*64+d] -> Vt[(bh*64+d)*2048+key]
// grid (64, 2, 64), block (32, 8)
// ---------------------------------------------------------------------------
__global__ __launch_bounds__(256) void vtrans_split_kernel(
    const float* __restrict__ V, __nv_bfloat16* __restrict__ Th,
    __nv_bfloat16* __restrict__ Tl)
{
    __shared__ float t[32][33];
    const int k0 = blockIdx.x * 32, d0 = blockIdx.y * 32;
    const int bh = blockIdx.z;
    const int b = bh >> 4, h = bh & 15;
    int tx = threadIdx.x, ty = threadIdx.y;
    #pragma unroll
    for (int j = 0; j < 32; j += 8)
        t[ty + j][tx] = V[(size_t)(b * NSEQ + k0 + ty + j) * D_IN + h * HDIM + d0 + tx];
    __syncthreads();
    #pragma unroll
    for (int j = 0; j < 32; j += 8) {
        float v = t[tx][ty + j];   // key = k0+tx, d = d0+ty+j
        __nv_bfloat16 hb = __float2bfloat16(v);
        size_t o = (size_t)(bh * HDIM + d0 + ty + j) * NSEQ + k0 + tx;
        Th[o] = hb;
        Tl[o] = __float2bfloat16(v - __bfloat162float(hb));
    }
}

// ---------------------------------------------------------------------------
// mma.sync helper (bf16 -> f32, m16n8k16, row.col)
// ---------------------------------------------------------------------------
__device__ __forceinline__ void mma_bf16(float* c, const uint32_t* a,
                                         uint32_t b0, uint32_t b1)
{
    asm volatile(
        "mma.sync.aligned.m16n8k16.row.col.f32.bf16.bf16.f32 "
        "{%0,%1,%2,%3}, {%4,%5,%6,%7}, {%8,%9}, {%0,%1,%2,%3};"
        : "+f"(c[0]), "+f"(c[1]), "+f"(c[2]), "+f"(c[3])
        : "r"(a[0]), "r"(a[1]), "r"(a[2]), "r"(a[3]), "r"(b0), "r"(b1));
}

// ---------------------------------------------------------------------------
// Split-bf16 tensor-core GEMM (unchanged from R3)
// ---------------------------------------------------------------------------
#define BK 16
#define ASTR 24

__global__ __launch_bounds__(256) void gemm_mma_kernel(
    const __nv_bfloat16* __restrict__ Ah, const __nv_bfloat16* __restrict__ Al,
    const __nv_bfloat16* __restrict__ Bh, const __nv_bfloat16* __restrict__ Bl,
    const float* __restrict__ bias, float* __restrict__ C)
{
    __shared__ __nv_bfloat16 sAh[128 * ASTR];
    __shared__ __nv_bfloat16 sAl[128 * ASTR];
    __shared__ __nv_bfloat16 sBh[128 * ASTR];
    __shared__ __nv_bfloat16 sBl[128 * ASTR];

    const int tid = threadIdx.x;
    const int wid = tid >> 5, lane = tid & 31;
    const int g = lane >> 2, tig = lane & 3;
    const int warpRow = (wid >> 1) * 32;
    const int warpCol = (wid & 1) * 64;
    const int rowBase = blockIdx.y * 128;
    const int colBase = blockIdx.x * 128;

    const __nv_bfloat16* gA0 = Ah + (size_t)rowBase * GK;
    const __nv_bfloat16* gA1 = Al + (size_t)rowBase * GK;
    const __nv_bfloat16* gB0 = Bh + (size_t)colBase * GK;
    const __nv_bfloat16* gB1 = Bl + (size_t)colBase * GK;

    float acc[2][8][4];
    #pragma unroll
    for (int mt = 0; mt < 2; mt++)
        #pragma unroll
        for (int nt = 0; nt < 8; nt++)
            #pragma unroll
            for (int j = 0; j < 4; j++) acc[mt][nt][j] = 0.f;

    const int lr = tid >> 1, lh = tid & 1;
    const size_t goff = (size_t)lr * GK + lh * 8;
    const int soff = lr * ASTR + lh * 8;

    for (int k0 = 0; k0 < GK; k0 += BK) {
        __syncthreads();
        *(uint4*)(sAh + soff) = *(const uint4*)(gA0 + goff + k0);
        *(uint4*)(sAl + soff) = *(const uint4*)(gA1 + goff + k0);
        *(uint4*)(sBh + soff) = *(const uint4*)(gB0 + goff + k0);
        *(uint4*)(sBl + soff) = *(const uint4*)(gB1 + goff + k0);
        __syncthreads();

        uint32_t ah[2][4], al[2][4];
        #pragma unroll
        for (int mt = 0; mt < 2; mt++) {
            const int r0 = warpRow + mt * 16 + g;
            ah[mt][0] = *(const uint32_t*)(sAh + r0 * ASTR + tig * 2);
            ah[mt][1] = *(const uint32_t*)(sAh + (r0 + 8) * ASTR + tig * 2);
            ah[mt][2] = *(const uint32_t*)(sAh + r0 * ASTR + tig * 2 + 8);
            ah[mt][3] = *(const uint32_t*)(sAh + (r0 + 8) * ASTR + tig * 2 + 8);
            al[mt][0] = *(const uint32_t*)(sAl + r0 * ASTR + tig * 2);
            al[mt][1] = *(const uint32_t*)(sAl + (r0 + 8) * ASTR + tig * 2);
            al[mt][2] = *(const uint32_t*)(sAl + r0 * ASTR + tig * 2 + 8);
            al[mt][3] = *(const uint32_t*)(sAl + (r0 + 8) * ASTR + tig * 2 + 8);
        }

        #pragma unroll
        for (int nt = 0; nt < 8; nt++) {
            const int n0 = warpCol + nt * 8 + g;
            uint32_t b0h = *(const uint32_t*)(sBh + n0 * ASTR + tig * 2);
            uint32_t b1h = *(const uint32_t*)(sBh + n0 * ASTR + tig * 2 + 8);
            uint32_t b0l = *(const uint32_t*)(sBl + n0 * ASTR + tig * 2);
            uint32_t b1l = *(const uint32_t*)(sBl + n0 * ASTR + tig * 2 + 8);
            #pragma unroll
            for (int mt = 0; mt < 2; mt++) {
                mma_bf16(acc[mt][nt], ah[mt], b0h, b1h);
                mma_bf16(acc[mt][nt], ah[mt], b0l, b1l);
                mma_bf16(acc[mt][nt], al[mt], b0h, b1h);
            }
        }
    }

    #pragma unroll
    for (int mt = 0; mt < 2; mt++) {
        #pragma unroll
        for (int nt = 0; nt < 8; nt++) {
            const int col = colBase + warpCol + nt * 8 + tig * 2;
            const int r0 = rowBase + warpRow + mt * 16 + g;
            float bx = 0.f, by = 0.f;
            if (bias) { bx = bias[col]; by = bias[col + 1]; }
            float2 v0 = {acc[mt][nt][0] + bx, acc[mt][nt][1] + by};
            float2 v1 = {acc[mt][nt][2] + bx, acc[mt][nt][3] + by};
            *(float2*)(C + (size_t)r0 * D_IN + col) = v0;
            *(float2*)(C + (size_t)(r0 + 8) * D_IN + col) = v1;
        }
    }
}

// ---------------------------------------------------------------------------
// Tensor-core causal flash attention, split-bf16, fixed-max softmax.
// 256 threads = 8 warps; warp w owns query rows q0+16w..+15. Key tiles of 64.
// grid (NSEQ/128, NHEAD, BATCH).
// ---------------------------------------------------------------------------
#define KSTR 72   // smem row stride (bf16)
#define EXP_C 0.1803368801111204f   // log2(e)/8

__global__ __launch_bounds__(256) void attn_mma_kernel(
    const __nv_bfloat16* __restrict__ Qh, const __nv_bfloat16* __restrict__ Ql,
    const __nv_bfloat16* __restrict__ Kh, const __nv_bfloat16* __restrict__ Kl,
    const __nv_bfloat16* __restrict__ Vth, const __nv_bfloat16* __restrict__ Vtl,
    float* __restrict__ Ctx)
{
    __shared__ __nv_bfloat16 sKh[64 * KSTR];
    __shared__ __nv_bfloat16 sKl[64 * KSTR];
    __shared__ __nv_bfloat16 sVh[64 * KSTR];
    __shared__ __nv_bfloat16 sVl[64 * KSTR];

    const int tid = threadIdx.x;
    const int wid = tid >> 5, lane = tid & 31;
    const int g = lane >> 2, tig = lane & 3;
    const int q0 = blockIdx.x * 128;
    const int h = blockIdx.y, b = blockIdx.z;
    const int bh = b * NHEAD + h;
    const int rA = q0 + wid * 16 + g;     // first row this thread covers
    const int rB = rA + 8;

    // Q fragments (hi/lo) straight from gmem, kept in registers
    const size_t qrow = (size_t)(b * NSEQ + q0 + wid * 16) * D_IN + h * HDIM;
    uint32_t qh[4][4], ql[4][4];
    #pragma unroll
    for (int ks = 0; ks < 4; ks++) {
        const int col = ks * 16 + tig * 2;
        qh[ks][0] = *(const uint32_t*)(Qh + qrow + (size_t)g * D_IN + col);
        qh[ks][1] = *(const uint32_t*)(Qh + qrow + (size_t)(g + 8) * D_IN + col);
        qh[ks][2] = *(const uint32_t*)(Qh + qrow + (size_t)g * D_IN + col + 8);
        qh[ks][3] = *(const uint32_t*)(Qh + qrow + (size_t)(g + 8) * D_IN + col + 8);
        ql[ks][0] = *(const uint32_t*)(Ql + qrow + (size_t)g * D_IN + col);
        ql[ks][1] = *(const uint32_t*)(Ql + qrow + (size_t)(g + 8) * D_IN + col);
        ql[ks][2] = *(const uint32_t*)(Ql + qrow + (size_t)g * D_IN + col + 8);
        ql[ks][3] = *(const uint32_t*)(Ql + qrow + (size_t)(g + 8) * D_IN + col + 8);
    }

    float O[8][4];
    #pragma unroll
    for (int nt = 0; nt < 8; nt++)
        #pragma unroll
        for (int j = 0; j < 4; j++) O[nt][j] = 0.f;
    float la = 0.f, lb = 0.f;

    const int ktmax = (q0 + 127) >> 6;
    const int lr = tid >> 3, lc = (tid & 7) * 8;   // tile-load coords (64 rows x 8 uint4)

    for (int kt = 0; kt <= ktmax; kt++) {
        const int k0 = kt * 64;
        __syncthreads();
        // stage K and Vt tiles (each 64 x 64 bf16, 2 rows per thread)
        #pragma unroll
        for (int i = 0; i < 2; i++) {
            const int r = lr + i * 32;
            const size_t gk = (size_t)(b * NSEQ + k0 + r) * D_IN + h * HDIM + lc;
            const size_t gv = (size_t)(bh * HDIM + r) * NSEQ + k0 + lc;
            *(uint4*)(sKh + r * KSTR + lc) = *(const uint4*)(Kh + gk);
            *(uint4*)(sKl + r * KSTR + lc) = *(const uint4*)(Kl + gk);
            *(uint4*)(sVh + r * KSTR + lc) = *(const uint4*)(Vth + gv);
            *(uint4*)(sVl + r * KSTR + lc) = *(const uint4*)(Vtl + gv);
        }
        __syncthreads();

        if (k0 > q0 + wid * 16 + 15) continue;   // fully masked for this warp

        // S = Q K^T (split 3-MMA)
        float S[8][4];
        #pragma unroll
        for (int nt = 0; nt < 8; nt++)
            #pragma unroll
            for (int j = 0; j < 4; j++) S[nt][j] = 0.f;

        #pragma unroll
        for (int ks = 0; ks < 4; ks++) {
            const int koff = ks * 16 + tig * 2;
            #pragma unroll
            for (int nt = 0; nt < 8; nt++) {
                const int n = nt * 8 + g;
                uint32_t b0h = *(const uint32_t*)(sKh + n * KSTR + koff);
                uint32_t b1h = *(const uint32_t*)(sKh + n * KSTR + koff + 8);
                uint32_t b0l = *(const uint32_t*)(sKl + n * KSTR + koff);
                uint32_t b1l = *(const uint32_t*)(sKl + n * KSTR + koff + 8);
                mma_bf16(S[nt], qh[ks], b0h, b1h);
                mma_bf16(S[nt], qh[ks], b0l, b1l);
                mma_bf16(S[nt], ql[ks], b0h, b1h);
            }
        }

        // softmax weights (fixed max = 0), pack P into A-fragments hi/lo
        uint32_t ph[4][4], pl[4][4];
        #pragma unroll
        for (int nt = 0; nt < 8; nt++) {
            const int c0 = k0 + nt * 8 + tig * 2;
            const int c1 = c0 + 1;
            float p0 = (c0 <= rA) ? fexp2(S[nt][0] * EXP_C) : 0.f;
            float p1 = (c1 <= rA) ? fexp2(S[nt][1] * EXP_C) : 0.f;
            float p2 = (c0 <= rB) ? fexp2(S[nt][2] * EXP_C) : 0.f;
            float p3 = (c1 <= rB) ? fexp2(S[nt][3] * EXP_C) : 0.f;
            la += p0 + p1;
            lb += p2 + p3;
            __nv_bfloat162 h01 = __float22bfloat162_rn(make_float2(p0, p1));
            __nv_bfloat162 h23 = __float22bfloat162_rn(make_float2(p2, p3));
            __nv_bfloat162 l01 = __float22bfloat162_rn(make_float2(
                p0 - __bfloat162float(h01.x), p1 - __bfloat162float(h01.y)));
            __nv_bfloat162 l23 = __float22bfloat162_rn(make_float2(
                p2 - __bfloat162float(h23.x), p3 - __bfloat162float(h23.y)));
            const int ks = nt >> 1, half = (nt & 1) * 2;
            ph[ks][half + 0] = *(uint32_t*)&h01;
            ph[ks][half + 1] = *(uint32_t*)&h23;
            pl[ks][half + 0] = *(uint32_t*)&l01;
            pl[ks][half + 1] = *(uint32_t*)&l23;
        }

        // O += P V (split 3-MMA); Vt smem is [d][key]
        #pragma unroll
        for (int ks = 0; ks < 4; ks++) {
            const int koff = ks * 16 + tig * 2;
            #pragma unroll
            for (int nt = 0; nt < 8; nt++) {
                const int n = nt * 8 + g;
                uint32_t b0h = *(const uint32_t*)(sVh + n * KSTR + koff);
                uint32_t b1h = *(const uint32_t*)(sVh + n * KSTR + koff + 8);
                uint32_t b0l = *(const uint32_t*)(sVl + n * KSTR + koff);
                uint32_t b1l = *(const uint32_t*)(sVl + n * KSTR + koff + 8);
                mma_bf16(O[nt], ph[ks], b0h, b1h);
                mma_bf16(O[nt], ph[ks], b0l, b1l);
                mma_bf16(O[nt], pl[ks], b0h, b1h);
            }
        }
    }

    // row-sum reduction across the 4 lanes sharing each row
    la += __shfl_xor_sync(0xFFFFFFFF, la, 1);
    la += __shfl_xor_sync(0xFFFFFFFF, la, 2);
    lb += __shfl_xor_sync(0xFFFFFFFF, lb, 1);
    lb += __shfl_xor_sync(0xFFFFFFFF, lb, 2);
    const float ia = 1.f / la, ib = 1.f / lb;

    #pragma unroll
    for (int nt = 0; nt < 8; nt++) {
        const int col = h * HDIM + nt * 8 + tig * 2;
        float2 vA = {O[nt][0] * ia, O[nt][1] * ia};
        float2 vB = {O[nt][2] * ib, O[nt][3] * ib};
        *(float2*)(Ctx + (size_t)(b * NSEQ + rA) * D_IN + col) = vA;
        *(float2*)(Ctx + (size_t)(b * NSEQ + rB) * D_IN + col) = vB;
    }
}

// ---------------------------------------------------------------------------
extern "C" void kernel_launch(void* const* d_in, const int* in_sizes, int n_in,
                              void* d_out, int out_size)
{
    const float* X  = (const float*)d_in[0];
    const float* Wq = (const float*)d_in[1];
    const float* Wk = (const float*)d_in[2];
    const float* Wv = (const float*)d_in[3];
    const float* Wo = (const float*)d_in[4];
    const float* bo = (const float*)d_in[5];
    float* out = (float*)d_out;

    float *pQ, *pK, *pV, *pC;
    __nv_bfloat16 *pXh, *pXl, *pWth, *pWtl;
    __nv_bfloat16 *pQh, *pQl, *pKh, *pKl, *pVth, *pVtl;
    cudaGetSymbolAddress((void**)&pQ, g_Q);
    cudaGetSymbolAddress((void**)&pK, g_K);
    cudaGetSymbolAddress((void**)&pV, g_V);
    cudaGetSymbolAddress((void**)&pC, g_C);
    cudaGetSymbolAddress((void**)&pXh, g_Xh);
    cudaGetSymbolAddress((void**)&pXl, g_Xl);
    cudaGetSymbolAddress((void**)&pWth, g_Wth);
    cudaGetSymbolAddress((void**)&pWtl, g_Wtl);
    cudaGetSymbolAddress((void**)&pQh, g_Qh);
    cudaGetSymbolAddress((void**)&pQl, g_Ql);
    cudaGetSymbolAddress((void**)&pKh, g_Kh);
    cudaGetSymbolAddress((void**)&pKl, g_Kl);
    cudaGetSymbolAddress((void**)&pVth, g_Vth);
    cudaGetSymbolAddress((void**)&pVtl, g_Vtl);

    const int splitBlocks = (MTOT * D_IN) / (256 * 4);    // 8192
    const dim3 trGrid(D_IN / 32, D_IN / 32), trBlk(32, 8);
    const dim3 gemmGrid(D_IN / 128, MTOT / 128);           // (8, 64)
    const dim3 vtGrid(NSEQ / 32, HDIM / 32, BATCH * NHEAD);

    split_kernel<<<splitBlocks, 256>>>(X, pXh, pXl);

    transpose_split_kernel<<<trGrid, trBlk>>>(Wq, pWth, pWtl);
    gemm_mma_kernel<<<gemmGrid, 256>>>(pXh, pXl, pWth, pWtl, nullptr, pQ);
    transpose_split_kernel<<<trGrid, trBlk>>>(Wk, pWth, pWtl);
    gemm_mma_kernel<<<gemmGrid, 256>>>(pXh, pXl, pWth, pWtl, nullptr, pK);
    transpose_split_kernel<<<trGrid, trBlk>>>(Wv, pWth, pWtl);
    gemm_mma_kernel<<<gemmGrid, 256>>>(pXh, pXl, pWth, pWtl, nullptr, pV);

    // attention operand prep
    split_kernel<<<splitBlocks, 256>>>(pQ, pQh, pQl);
    split_kernel<<<splitBlocks, 256>>>(pK, pKh, pKl);
    vtrans_split_kernel<<<vtGrid, trBlk>>>(pV, pVth, pVtl);

    attn_mma_kernel<<<dim3(NSEQ / 128, NHEAD, BATCH), 256>>>(
        pQh, pQl, pKh, pKl, pVth, pVtl, pC);

    split_kernel<<<splitBlocks, 256>>>(pC, pXh, pXl);
    transpose_split_kernel<<<trGrid, trBlk>>>(Wo, pWth, pWtl);
    gemm_mma_kernel<<<gemmGrid, 256>>>(pXh, pXl, pWth, pWtl, bo, out);
}

// round 6
// speedup vs baseline: 2.8879x; 1.1173x over previous
#include <cuda_runtime.h>
#include <cuda_bf16.h>
#include <cstdint>

// Problem constants
#define D_IN   1024
#define NSEQ   2048
#define BATCH  4
#define NHEAD  16
#define HDIM   64
#define MTOT   (BATCH*NSEQ)   // 8192
#define GK     1024

// ---------------------------------------------------------------------------
// Scratch (no cudaMalloc allowed)
// ---------------------------------------------------------------------------
__device__ float g_V[(size_t)MTOT * D_IN];
__device__ __nv_bfloat16 g_Xh[(size_t)MTOT * D_IN];
__device__ __nv_bfloat16 g_Xl[(size_t)MTOT * D_IN];
__device__ __nv_bfloat16 g_Ch[(size_t)MTOT * D_IN];   // ctx hi (attention out)
__device__ __nv_bfloat16 g_Cl[(size_t)MTOT * D_IN];   // ctx lo
__device__ __nv_bfloat16 g_Wth[(size_t)D_IN * D_IN];
__device__ __nv_bfloat16 g_Wtl[(size_t)D_IN * D_IN];
__device__ __nv_bfloat16 g_Qh[(size_t)MTOT * D_IN];
__device__ __nv_bfloat16 g_Ql[(size_t)MTOT * D_IN];
__device__ __nv_bfloat16 g_Kh[(size_t)MTOT * D_IN];
__device__ __nv_bfloat16 g_Kl[(size_t)MTOT * D_IN];
__device__ __nv_bfloat16 g_Vth[(size_t)BATCH * NHEAD * HDIM * NSEQ];
__device__ __nv_bfloat16 g_Vtl[(size_t)BATCH * NHEAD * HDIM * NSEQ];

__device__ __forceinline__ float fexp2(float x) {
    float r;
    asm("ex2.approx.f32 %0, %1;" : "=f"(r) : "f"(x));
    return r;
}
__device__ __forceinline__ uint32_t smem_u32(const void* p) {
    uint32_t a;
    asm("{ .reg .u64 t; cvta.to.shared.u64 t, %1; cvt.u32.u64 %0, t; }" : "=r"(a) : "l"(p));
    return a;
}
__device__ __forceinline__ void cp16(uint32_t saddr, const void* gptr) {
    asm volatile("cp.async.cg.shared.global [%0], [%1], 16;" :: "r"(saddr), "l"(gptr));
}

// ---------------------------------------------------------------------------
// Split fp32 -> bf16 hi + lo (used only for X)
// ---------------------------------------------------------------------------
__global__ __launch_bounds__(256) void split_kernel(
    const float* __restrict__ x, __nv_bfloat16* __restrict__ hi,
    __nv_bfloat16* __restrict__ lo)
{
    size_t i = (size_t)blockIdx.x * 256 + threadIdx.x;
    float4 v = ((const float4*)x)[i];
    __nv_bfloat16 h0 = __float2bfloat16(v.x), h1 = __float2bfloat16(v.y);
    __nv_bfloat16 h2 = __float2bfloat16(v.z), h3 = __float2bfloat16(v.w);
    __nv_bfloat16 l0 = __float2bfloat16(v.x - __bfloat162float(h0));
    __nv_bfloat16 l1 = __float2bfloat16(v.y - __bfloat162float(h1));
    __nv_bfloat16 l2 = __float2bfloat16(v.z - __bfloat162float(h2));
    __nv_bfloat16 l3 = __float2bfloat16(v.w - __bfloat162float(h3));
    __nv_bfloat162 hv0{h0, h1}, hv1{h2, h3}, lv0{l0, l1}, lv1{l2, l3};
    ((__nv_bfloat162*)hi)[i * 2 + 0] = hv0;
    ((__nv_bfloat162*)hi)[i * 2 + 1] = hv1;
    ((__nv_bfloat162*)lo)[i * 2 + 0] = lv0;
    ((__nv_bfloat162*)lo)[i * 2 + 1] = lv1;
}

// ---------------------------------------------------------------------------
// Transpose + split weights: W[K,N] fp32 -> Wt[N,K] bf16 hi/lo
// ---------------------------------------------------------------------------
__global__ __launch_bounds__(256) void transpose_split_kernel(
    const float* __restrict__ W, __nv_bfloat16* __restrict__ Th,
    __nv_bfloat16* __restrict__ Tl)
{
    __shared__ float t[32][33];
    int x0 = blockIdx.x * 32, y0 = blockIdx.y * 32;
    int tx = threadIdx.x, ty = threadIdx.y;  // (32, 8)
    #pragma unroll
    for (int j = 0; j < 32; j += 8)
        t[ty + j][tx] = W[(size_t)(y0 + ty + j) * D_IN + x0 + tx];
    __syncthreads();
    #pragma unroll
    for (int j = 0; j < 32; j += 8) {
        float v = t[tx][ty + j];
        __nv_bfloat16 h = __float2bfloat16(v);
        Th[(size_t)(x0 + ty + j) * D_IN + y0 + tx] = h;
        Tl[(size_t)(x0 + ty + j) * D_IN + y0 + tx] = __float2bfloat16(v - __bfloat162float(h));
    }
}

// ---------------------------------------------------------------------------
// Per-head V transpose+split: V[b*2048+key][h*64+d] -> Vt[(bh*64+d)*2048+key]
// ---------------------------------------------------------------------------
__global__ __launch_bounds__(256) void vtrans_split_kernel(
    const float* __restrict__ V, __nv_bfloat16* __restrict__ Th,
    __nv_bfloat16* __restrict__ Tl)
{
    __shared__ float t[32][33];
    const int k0 = blockIdx.x * 32, d0 = blockIdx.y * 32;
    const int bh = blockIdx.z;
    const int b = bh >> 4, h = bh & 15;
    int tx = threadIdx.x, ty = threadIdx.y;
    #pragma unroll
    for (int j = 0; j < 32; j += 8)
        t[ty + j][tx] = V[(size_t)(b * NSEQ + k0 + ty + j) * D_IN + h * HDIM + d0 + tx];
    __syncthreads();
    #pragma unroll
    for (int j = 0; j < 32; j += 8) {
        float v = t[tx][ty + j];
        __nv_bfloat16 hb = __float2bfloat16(v);
        size_t o = (size_t)(bh * HDIM + d0 + ty + j) * NSEQ + k0 + tx;
        Th[o] = hb;
        Tl[o] = __float2bfloat16(v - __bfloat162float(hb));
    }
}

// ---------------------------------------------------------------------------
// mma.sync helper
// ---------------------------------------------------------------------------
__device__ __forceinline__ void mma_bf16(float* c, const uint32_t* a,
                                         uint32_t b0, uint32_t b1)
{
    asm volatile(
        "mma.sync.aligned.m16n8k16.row.col.f32.bf16.bf16.f32 "
        "{%0,%1,%2,%3}, {%4,%5,%6,%7}, {%8,%9}, {%0,%1,%2,%3};"
        : "+f"(c[0]), "+f"(c[1]), "+f"(c[2]), "+f"(c[3])
        : "r"(a[0]), "r"(a[1]), "r"(a[2]), "r"(a[3]), "r"(b0), "r"(b1));
}

// ---------------------------------------------------------------------------
// Pipelined split-bf16 GEMM with cp.async double buffering.
// CTA tile 128x128, BK=32, 2 stages. Output: fp32 (+bias) OR split bf16 hi/lo.
// ---------------------------------------------------------------------------
#define BK2 32
#define AS2 40                       // smem row stride in bf16 (80B)
#define MAT_E (128 * AS2)            // 5120 elems per matrix
#define STG_E (4 * MAT_E)            // per stage: Ah, Al, Bh, Bl
#define GSMEM (2 * STG_E * 2)        // bytes (2 stages, 2B/elem)

__global__ __launch_bounds__(256) void gemm_mma2_kernel(
    const __nv_bfloat16* __restrict__ Ah_, const __nv_bfloat16* __restrict__ Al_,
    const __nv_bfloat16* __restrict__ Bh_, const __nv_bfloat16* __restrict__ Bl_,
    const float* __restrict__ bias, float* __restrict__ C,
    __nv_bfloat16* __restrict__ Ch, __nv_bfloat16* __restrict__ Cl)
{
    extern __shared__ __nv_bfloat16 smem[];
    const int tid = threadIdx.x;
    const int wid = tid >> 5, lane = tid & 31;
    const int g = lane >> 2, tig = lane & 3;
    const int warpRow = (wid >> 1) * 32;
    const int warpCol = (wid & 1) * 64;
    const int rowBase = blockIdx.y * 128;
    const int colBase = blockIdx.x * 128;

    const __nv_bfloat16* gA0 = Ah_ + (size_t)rowBase * GK;
    const __nv_bfloat16* gA1 = Al_ + (size_t)rowBase * GK;
    const __nv_bfloat16* gB0 = Bh_ + (size_t)colBase * GK;
    const __nv_bfloat16* gB1 = Bl_ + (size_t)colBase * GK;

    float acc[2][8][4];
    #pragma unroll
    for (int mt = 0; mt < 2; mt++)
        #pragma unroll
        for (int nt = 0; nt < 8; nt++)
            #pragma unroll
            for (int j = 0; j < 4; j++) acc[mt][nt][j] = 0.f;

    const int lr = tid >> 1, lh = tid & 1;           // row 0..127, half 0..1
    const uint32_t sbase = smem_u32(smem);
    const size_t gbase = (size_t)lr * GK + lh * 16;  // + k0 + c*8
    const uint32_t sb0 = sbase + (lr * AS2 + lh * 16) * 2;  // + c*16 bytes

    const int NIT = GK / BK2;  // 32

    // prologue: stage 0
    {
        #pragma unroll
        for (int c = 0; c < 2; c++) {
            cp16(sb0 + c * 16 + 0 * MAT_E * 2, gA0 + gbase + c * 8);
            cp16(sb0 + c * 16 + 1 * MAT_E * 2, gA1 + gbase + c * 8);
            cp16(sb0 + c * 16 + 2 * MAT_E * 2, gB0 + gbase + c * 8);
            cp16(sb0 + c * 16 + 3 * MAT_E * 2, gB1 + gbase + c * 8);
        }
        asm volatile("cp.async.commit_group;" ::: "memory");
    }

    for (int it = 0; it < NIT; it++) {
        if (it + 1 < NIT) {
            const int k0 = (it + 1) * BK2;
            const uint32_t sb = sb0 + ((it + 1) & 1) * STG_E * 2;
            #pragma unroll
            for (int c = 0; c < 2; c++) {
                cp16(sb + c * 16 + 0 * MAT_E * 2, gA0 + gbase + k0 + c * 8);
                cp16(sb + c * 16 + 1 * MAT_E * 2, gA1 + gbase + k0 + c * 8);
                cp16(sb + c * 16 + 2 * MAT_E * 2, gB0 + gbase + k0 + c * 8);
                cp16(sb + c * 16 + 3 * MAT_E * 2, gB1 + gbase + k0 + c * 8);
            }
            asm volatile("cp.async.commit_group;" ::: "memory");
            asm volatile("cp.async.wait_group 1;" ::: "memory");
        } else {
            asm volatile("cp.async.wait_group 0;" ::: "memory");
        }
        __syncthreads();

        const __nv_bfloat16* cAh = smem + (it & 1) * STG_E;
        const __nv_bfloat16* cAl = cAh + MAT_E;
        const __nv_bfloat16* cBh = cAh + 2 * MAT_E;
        const __nv_bfloat16* cBl = cAh + 3 * MAT_E;

        #pragma unroll
        for (int ks = 0; ks < 2; ks++) {
            const int koff = ks * 16 + tig * 2;
            uint32_t ah[2][4], al[2][4];
            #pragma unroll
            for (int mt = 0; mt < 2; mt++) {
                const int r0 = warpRow + mt * 16 + g;
                ah[mt][0] = *(const uint32_t*)(cAh + r0 * AS2 + koff);
                ah[mt][1] = *(const uint32_t*)(cAh + (r0 + 8) * AS2 + koff);
                ah[mt][2] = *(const uint32_t*)(cAh + r0 * AS2 + koff + 8);
                ah[mt][3] = *(const uint32_t*)(cAh + (r0 + 8) * AS2 + koff + 8);
                al[mt][0] = *(const uint32_t*)(cAl + r0 * AS2 + koff);
                al[mt][1] = *(const uint32_t*)(cAl + (r0 + 8) * AS2 + koff);
                al[mt][2] = *(const uint32_t*)(cAl + r0 * AS2 + koff + 8);
                al[mt][3] = *(const uint32_t*)(cAl + (r0 + 8) * AS2 + koff + 8);
            }
            #pragma unroll
            for (int nt = 0; nt < 8; nt++) {
                const int n0 = warpCol + nt * 8 + g;
                uint32_t b0h = *(const uint32_t*)(cBh + n0 * AS2 + koff);
                uint32_t b1h = *(const uint32_t*)(cBh + n0 * AS2 + koff + 8);
                uint32_t b0l = *(const uint32_t*)(cBl + n0 * AS2 + koff);
                uint32_t b1l = *(const uint32_t*)(cBl + n0 * AS2 + koff + 8);
                #pragma unroll
                for (int mt = 0; mt < 2; mt++) {
                    mma_bf16(acc[mt][nt], ah[mt], b0h, b1h);
                    mma_bf16(acc[mt][nt], ah[mt], b0l, b1l);
                    mma_bf16(acc[mt][nt], al[mt], b0h, b1h);
                }
            }
        }
        __syncthreads();
    }

    // epilogue
    #pragma unroll
    for (int mt = 0; mt < 2; mt++) {
        #pragma unroll
        for (int nt = 0; nt < 8; nt++) {
            const int col = colBase + warpCol + nt * 8 + tig * 2;
            const int r0 = rowBase + warpRow + mt * 16 + g;
            if (C) {
                float bx = 0.f, by = 0.f;
                if (bias) { bx = bias[col]; by = bias[col + 1]; }
                float2 v0 = {acc[mt][nt][0] + bx, acc[mt][nt][1] + by};
                float2 v1 = {acc[mt][nt][2] + bx, acc[mt][nt][3] + by};
                *(float2*)(C + (size_t)r0 * D_IN + col) = v0;
                *(float2*)(C + (size_t)(r0 + 8) * D_IN + col) = v1;
            } else {
                float2 v0 = {acc[mt][nt][0], acc[mt][nt][1]};
                float2 v1 = {acc[mt][nt][2], acc[mt][nt][3]};
                __nv_bfloat162 h0 = __float22bfloat162_rn(v0);
                __nv_bfloat162 h1 = __float22bfloat162_rn(v1);
                __nv_bfloat162 l0 = __float22bfloat162_rn(make_float2(
                    v0.x - __bfloat162float(h0.x), v0.y - __bfloat162float(h0.y)));
                __nv_bfloat162 l1 = __float22bfloat162_rn(make_float2(
                    v1.x - __bfloat162float(h1.x), v1.y - __bfloat162float(h1.y)));
                *(uint32_t*)(Ch + (size_t)r0 * D_IN + col) = *(uint32_t*)&h0;
                *(uint32_t*)(Ch + (size_t)(r0 + 8) * D_IN + col) = *(uint32_t*)&h1;
                *(uint32_t*)(Cl + (size_t)r0 * D_IN + col) = *(uint32_t*)&l0;
                *(uint32_t*)(Cl + (size_t)(r0 + 8) * D_IN + col) = *(uint32_t*)&l1;
            }
        }
    }
}

// ---------------------------------------------------------------------------
// Tensor-core causal flash attention (unchanged math; writes split ctx)
// ---------------------------------------------------------------------------
#define KSTR 72
#define EXP_C 0.1803368801111204f   // log2(e)/8

__global__ __launch_bounds__(256) void attn_mma_kernel(
    const __nv_bfloat16* __restrict__ Qh, const __nv_bfloat16* __restrict__ Ql,
    const __nv_bfloat16* __restrict__ Kh, const __nv_bfloat16* __restrict__ Kl,
    const __nv_bfloat16* __restrict__ Vth, const __nv_bfloat16* __restrict__ Vtl,
    __nv_bfloat16* __restrict__ Ch, __nv_bfloat16* __restrict__ Cl)
{
    __shared__ __nv_bfloat16 sKh[64 * KSTR];
    __shared__ __nv_bfloat16 sKl[64 * KSTR];
    __shared__ __nv_bfloat16 sVh[64 * KSTR];
    __shared__ __nv_bfloat16 sVl[64 * KSTR];

    const int tid = threadIdx.x;
    const int wid = tid >> 5, lane = tid & 31;
    const int g = lane >> 2, tig = lane & 3;
    const int q0 = blockIdx.x * 128;
    const int h = blockIdx.y, b = blockIdx.z;
    const int bh = b * NHEAD + h;
    const int rA = q0 + wid * 16 + g;
    const int rB = rA + 8;

    const size_t qrow = (size_t)(b * NSEQ + q0 + wid * 16) * D_IN + h * HDIM;
    uint32_t qh[4][4], ql[4][4];
    #pragma unroll
    for (int ks = 0; ks < 4; ks++) {
        const int col = ks * 16 + tig * 2;
        qh[ks][0] = *(const uint32_t*)(Qh + qrow + (size_t)g * D_IN + col);
        qh[ks][1] = *(const uint32_t*)(Qh + qrow + (size_t)(g + 8) * D_IN + col);
        qh[ks][2] = *(const uint32_t*)(Qh + qrow + (size_t)g * D_IN + col + 8);
        qh[ks][3] = *(const uint32_t*)(Qh + qrow + (size_t)(g + 8) * D_IN + col + 8);
        ql[ks][0] = *(const uint32_t*)(Ql + qrow + (size_t)g * D_IN + col);
        ql[ks][1] = *(const uint32_t*)(Ql + qrow + (size_t)(g + 8) * D_IN + col);
        ql[ks][2] = *(const uint32_t*)(Ql + qrow + (size_t)g * D_IN + col + 8);
        ql[ks][3] = *(const uint32_t*)(Ql + qrow + (size_t)(g + 8) * D_IN + col + 8);
    }

    float O[8][4];
    #pragma unroll
    for (int nt = 0; nt < 8; nt++)
        #pragma unroll
        for (int j = 0; j < 4; j++) O[nt][j] = 0.f;
    float la = 0.f, lb = 0.f;

    const int ktmax = (q0 + 127) >> 6;
    const int lr = tid >> 3, lc = (tid & 7) * 8;

    for (int kt = 0; kt <= ktmax; kt++) {
        const int k0 = kt * 64;
        __syncthreads();
        #pragma unroll
        for (int i = 0; i < 2; i++) {
            const int r = lr + i * 32;
            const size_t gk = (size_t)(b * NSEQ + k0 + r) * D_IN + h * HDIM + lc;
            const size_t gv = (size_t)(bh * HDIM + r) * NSEQ + k0 + lc;
            *(uint4*)(sKh + r * KSTR + lc) = *(const uint4*)(Kh + gk);
            *(uint4*)(sKl + r * KSTR + lc) = *(const uint4*)(Kl + gk);
            *(uint4*)(sVh + r * KSTR + lc) = *(const uint4*)(Vth + gv);
            *(uint4*)(sVl + r * KSTR + lc) = *(const uint4*)(Vtl + gv);
        }
        __syncthreads();

        if (k0 > q0 + wid * 16 + 15) continue;

        float S[8][4];
        #pragma unroll
        for (int nt = 0; nt < 8; nt++)
            #pragma unroll
            for (int j = 0; j < 4; j++) S[nt][j] = 0.f;

        #pragma unroll
        for (int ks = 0; ks < 4; ks++) {
            const int koff = ks * 16 + tig * 2;
            #pragma unroll
            for (int nt = 0; nt < 8; nt++) {
                const int n = nt * 8 + g;
                uint32_t b0h = *(const uint32_t*)(sKh + n * KSTR + koff);
                uint32_t b1h = *(const uint32_t*)(sKh + n * KSTR + koff + 8);
                uint32_t b0l = *(const uint32_t*)(sKl + n * KSTR + koff);
                uint32_t b1l = *(const uint32_t*)(sKl + n * KSTR + koff + 8);
                mma_bf16(S[nt], qh[ks], b0h, b1h);
                mma_bf16(S[nt], qh[ks], b0l, b1l);
                mma_bf16(S[nt], ql[ks], b0h, b1h);
            }
        }

        uint32_t ph[4][4], pl[4][4];
        #pragma unroll
        for (int nt = 0; nt < 8; nt++) {
            const int c0 = k0 + nt * 8 + tig * 2;
            const int c1 = c0 + 1;
            float p0 = (c0 <= rA) ? fexp2(S[nt][0] * EXP_C) : 0.f;
            float p1 = (c1 <= rA) ? fexp2(S[nt][1] * EXP_C) : 0.f;
            float p2 = (c0 <= rB) ? fexp2(S[nt][2] * EXP_C) : 0.f;
            float p3 = (c1 <= rB) ? fexp2(S[nt][3] * EXP_C) : 0.f;
            la += p0 + p1;
            lb += p2 + p3;
            __nv_bfloat162 h01 = __float22bfloat162_rn(make_float2(p0, p1));
            __nv_bfloat162 h23 = __float22bfloat162_rn(make_float2(p2, p3));
            __nv_bfloat162 l01 = __float22bfloat162_rn(make_float2(
                p0 - __bfloat162float(h01.x), p1 - __bfloat162float(h01.y)));
            __nv_bfloat162 l23 = __float22bfloat162_rn(make_float2(
                p2 - __bfloat162float(h23.x), p3 - __bfloat162float(h23.y)));
            const int ks = nt >> 1, half = (nt & 1) * 2;
            ph[ks][half + 0] = *(uint32_t*)&h01;
            ph[ks][half + 1] = *(uint32_t*)&h23;
            pl[ks][half + 0] = *(uint32_t*)&l01;
            pl[ks][half + 1] = *(uint32_t*)&l23;
        }

        #pragma unroll
        for (int ks = 0; ks < 4; ks++) {
            const int koff = ks * 16 + tig * 2;
            #pragma unroll
            for (int nt = 0; nt < 8; nt++) {
                const int n = nt * 8 + g;
                uint32_t b0h = *(const uint32_t*)(sVh + n * KSTR + koff);
                uint32_t b1h = *(const uint32_t*)(sVh + n * KSTR + koff + 8);
                uint32_t b0l = *(const uint32_t*)(sVl + n * KSTR + koff);
                uint32_t b1l = *(const uint32_t*)(sVl + n * KSTR + koff + 8);
                mma_bf16(O[nt], ph[ks], b0h, b1h);
                mma_bf16(O[nt], ph[ks], b0l, b1l);
                mma_bf16(O[nt], pl[ks], b0h, b1h);
            }
        }
    }

    la += __shfl_xor_sync(0xFFFFFFFF, la, 1);
    la += __shfl_xor_sync(0xFFFFFFFF, la, 2);
    lb += __shfl_xor_sync(0xFFFFFFFF, lb, 1);
    lb += __shfl_xor_sync(0xFFFFFFFF, lb, 2);
    const float ia = 1.f / la, ib = 1.f / lb;

    #pragma unroll
    for (int nt = 0; nt < 8; nt++) {
        const int col = h * HDIM + nt * 8 + tig * 2;
        float2 vA = {O[nt][0] * ia, O[nt][1] * ia};
        float2 vB = {O[nt][2] * ib, O[nt][3] * ib};
        __nv_bfloat162 hA = __float22bfloat162_rn(vA);
        __nv_bfloat162 hB = __float22bfloat162_rn(vB);
        __nv_bfloat162 lA = __float22bfloat162_rn(make_float2(
            vA.x - __bfloat162float(hA.x), vA.y - __bfloat162float(hA.y)));
        __nv_bfloat162 lB = __float22bfloat162_rn(make_float2(
            vB.x - __bfloat162float(hB.x), vB.y - __bfloat162float(hB.y)));
        *(uint32_t*)(Ch + (size_t)(b * NSEQ + rA) * D_IN + col) = *(uint32_t*)&hA;
        *(uint32_t*)(Ch + (size_t)(b * NSEQ + rB) * D_IN + col) = *(uint32_t*)&hB;
        *(uint32_t*)(Cl + (size_t)(b * NSEQ + rA) * D_IN + col) = *(uint32_t*)&lA;
        *(uint32_t*)(Cl + (size_t)(b * NSEQ + rB) * D_IN + col) = *(uint32_t*)&lB;
    }
}

// ---------------------------------------------------------------------------
extern "C" void kernel_launch(void* const* d_in, const int* in_sizes, int n_in,
                              void* d_out, int out_size)
{
    const float* X  = (const float*)d_in[0];
    const float* Wq = (const float*)d_in[1];
    const float* Wk = (const float*)d_in[2];
    const float* Wv = (const float*)d_in[3];
    const float* Wo = (const float*)d_in[4];
    const float* bo = (const float*)d_in[5];
    float* out = (float*)d_out;

    float* pV;
    __nv_bfloat16 *pXh, *pXl, *pCh, *pCl, *pWth, *pWtl;
    __nv_bfloat16 *pQh, *pQl, *pKh, *pKl, *pVth, *pVtl;
    cudaGetSymbolAddress((void**)&pV, g_V);
    cudaGetSymbolAddress((void**)&pXh, g_Xh);
    cudaGetSymbolAddress((void**)&pXl, g_Xl);
    cudaGetSymbolAddress((void**)&pCh, g_Ch);
    cudaGetSymbolAddress((void**)&pCl, g_Cl);
    cudaGetSymbolAddress((void**)&pWth, g_Wth);
    cudaGetSymbolAddress((void**)&pWtl, g_Wtl);
    cudaGetSymbolAddress((void**)&pQh, g_Qh);
    cudaGetSymbolAddress((void**)&pQl, g_Ql);
    cudaGetSymbolAddress((void**)&pKh, g_Kh);
    cudaGetSymbolAddress((void**)&pKl, g_Kl);
    cudaGetSymbolAddress((void**)&pVth, g_Vth);
    cudaGetSymbolAddress((void**)&pVtl, g_Vtl);

    static bool attrs_set = false;
    if (!attrs_set) {
        cudaFuncSetAttribute(gemm_mma2_kernel,
                             cudaFuncAttributeMaxDynamicSharedMemorySize, GSMEM);
        attrs_set = true;
    }

    const int splitBlocks = (MTOT * D_IN) / (256 * 4);
    const dim3 trGrid(D_IN / 32, D_IN / 32), trBlk(32, 8);
    const dim3 gemmGrid(D_IN / 128, MTOT / 128);
    const dim3 vtGrid(NSEQ / 32, HDIM / 32, BATCH * NHEAD);

    split_kernel<<<splitBlocks, 256>>>(X, pXh, pXl);

    // Q, K projections -> split bf16 directly
    transpose_split_kernel<<<trGrid, trBlk>>>(Wq, pWth, pWtl);
    gemm_mma2_kernel<<<gemmGrid, 256, GSMEM>>>(pXh, pXl, pWth, pWtl,
                                               nullptr, nullptr, pQh, pQl);
    transpose_split_kernel<<<trGrid, trBlk>>>(Wk, pWth, pWtl);
    gemm_mma2_kernel<<<gemmGrid, 256, GSMEM>>>(pXh, pXl, pWth, pWtl,
                                               nullptr, nullptr, pKh, pKl);
    // V projection -> fp32 (transposed+split next)
    transpose_split_kernel<<<trGrid, trBlk>>>(Wv, pWth, pWtl);
    gemm_mma2_kernel<<<gemmGrid, 256, GSMEM>>>(pXh, pXl, pWth, pWtl,
                                               nullptr, pV, nullptr, nullptr);
    vtrans_split_kernel<<<vtGrid, trBlk>>>(pV, pVth, pVtl);

    // attention -> split ctx
    attn_mma_kernel<<<dim3(NSEQ / 128, NHEAD, BATCH), 256>>>(
        pQh, pQl, pKh, pKl, pVth, pVtl, pCh, pCl);

    // output projection + bias
    transpose_split_kernel<<<trGrid, trBlk>>>(Wo, pWth, pWtl);
    gemm_mma2_kernel<<<gemmGrid, 256, GSMEM>>>(pCh, pCl, pWth, pWtl,
                                               bo, out, nullptr, nullptr);
}

// round 7
// speedup vs baseline: 2.9269x; 1.0135x over previous
#include <cuda_runtime.h>
#include <cuda_bf16.h>
#include <cstdint>

// Problem constants
#define D_IN   1024
#define NSEQ   2048
#define BATCH  4
#define NHEAD  16
#define HDIM   64
#define MTOT   (BATCH*NSEQ)   // 8192
#define GK     1024
#define NQKV   3072

// ---------------------------------------------------------------------------
// Scratch (no cudaMalloc allowed)
// ---------------------------------------------------------------------------
__device__ float g_V[(size_t)MTOT * D_IN];
__device__ __nv_bfloat16 g_Xh[(size_t)MTOT * D_IN];
__device__ __nv_bfloat16 g_Xl[(size_t)MTOT * D_IN];
__device__ __nv_bfloat16 g_Ch[(size_t)MTOT * D_IN];
__device__ __nv_bfloat16 g_Cl[(size_t)MTOT * D_IN];
__device__ __nv_bfloat16 g_Wth[(size_t)NQKV * D_IN];   // fused Wq|Wk|Wv (Wo reuses rows 0-1023)
__device__ __nv_bfloat16 g_Wtl[(size_t)NQKV * D_IN];
__device__ __nv_bfloat16 g_Qh[(size_t)MTOT * D_IN];
__device__ __nv_bfloat16 g_Ql[(size_t)MTOT * D_IN];
__device__ __nv_bfloat16 g_Kh[(size_t)MTOT * D_IN];
__device__ __nv_bfloat16 g_Kl[(size_t)MTOT * D_IN];
__device__ __nv_bfloat16 g_Vth[(size_t)BATCH * NHEAD * HDIM * NSEQ];
__device__ __nv_bfloat16 g_Vtl[(size_t)BATCH * NHEAD * HDIM * NSEQ];

__device__ __forceinline__ float fexp2(float x) {
    float r;
    asm("ex2.approx.f32 %0, %1;" : "=f"(r) : "f"(x));
    return r;
}
__device__ __forceinline__ uint32_t smem_u32(const void* p) {
    uint32_t a;
    asm("{ .reg .u64 t; cvta.to.shared.u64 t, %1; cvt.u32.u64 %0, t; }" : "=r"(a) : "l"(p));
    return a;
}
__device__ __forceinline__ void cp16(uint32_t saddr, const void* gptr) {
    asm volatile("cp.async.cg.shared.global [%0], [%1], 16;" :: "r"(saddr), "l"(gptr));
}
__device__ __forceinline__ void ldsm4(uint32_t* r, uint32_t saddr) {
    asm volatile("ldmatrix.sync.aligned.m8n8.x4.shared.b16 {%0,%1,%2,%3}, [%4];"
        : "=r"(r[0]), "=r"(r[1]), "=r"(r[2]), "=r"(r[3]) : "r"(saddr));
}
__device__ __forceinline__ void mma_bf16(float* c, const uint32_t* a,
                                         uint32_t b0, uint32_t b1)
{
    asm volatile(
        "mma.sync.aligned.m16n8k16.row.col.f32.bf16.bf16.f32 "
        "{%0,%1,%2,%3}, {%4,%5,%6,%7}, {%8,%9}, {%0,%1,%2,%3};"
        : "+f"(c[0]), "+f"(c[1]), "+f"(c[2]), "+f"(c[3])
        : "r"(a[0]), "r"(a[1]), "r"(a[2]), "r"(a[3]), "r"(b0), "r"(b1));
}

// ---------------------------------------------------------------------------
// Split fp32 -> bf16 hi + lo (used only for X)
// ---------------------------------------------------------------------------
__global__ __launch_bounds__(256) void split_kernel(
    const float* __restrict__ x, __nv_bfloat16* __restrict__ hi,
    __nv_bfloat16* __restrict__ lo)
{
    size_t i = (size_t)blockIdx.x * 256 + threadIdx.x;
    float4 v = ((const float4*)x)[i];
    __nv_bfloat16 h0 = __float2bfloat16(v.x), h1 = __float2bfloat16(v.y);
    __nv_bfloat16 h2 = __float2bfloat16(v.z), h3 = __float2bfloat16(v.w);
    __nv_bfloat16 l0 = __float2bfloat16(v.x - __bfloat162float(h0));
    __nv_bfloat16 l1 = __float2bfloat16(v.y - __bfloat162float(h1));
    __nv_bfloat16 l2 = __float2bfloat16(v.z - __bfloat162float(h2));
    __nv_bfloat16 l3 = __float2bfloat16(v.w - __bfloat162float(h3));
    __nv_bfloat162 hv0{h0, h1}, hv1{h2, h3}, lv0{l0, l1}, lv1{l2, l3};
    ((__nv_bfloat162*)hi)[i * 2 + 0] = hv0;
    ((__nv_bfloat162*)hi)[i * 2 + 1] = hv1;
    ((__nv_bfloat162*)lo)[i * 2 + 0] = lv0;
    ((__nv_bfloat162*)lo)[i * 2 + 1] = lv1;
}

// ---------------------------------------------------------------------------
// Transpose + split weights: W[K,1024] fp32 -> Wt[rowOff+N][K] bf16 hi/lo
// ---------------------------------------------------------------------------
__global__ __launch_bounds__(256) void transpose_split_kernel(
    const float* __restrict__ W, __nv_bfloat16* __restrict__ Th,
    __nv_bfloat16* __restrict__ Tl, int rowOff)
{
    __shared__ float t[32][33];
    int x0 = blockIdx.x * 32, y0 = blockIdx.y * 32;
    int tx = threadIdx.x, ty = threadIdx.y;  // (32, 8)
    #pragma unroll
    for (int j = 0; j < 32; j += 8)
        t[ty + j][tx] = W[(size_t)(y0 + ty + j) * D_IN + x0 + tx];
    __syncthreads();
    #pragma unroll
    for (int j = 0; j < 32; j += 8) {
        float v = t[tx][ty + j];
        __nv_bfloat16 h = __float2bfloat16(v);
        size_t o = (size_t)(rowOff + x0 + ty + j) * GK + y0 + tx;
        Th[o] = h;
        Tl[o] = __float2bfloat16(v - __bfloat162float(h));
    }
}

// ---------------------------------------------------------------------------
// Per-head V transpose+split
// ---------------------------------------------------------------------------
__global__ __launch_bounds__(256) void vtrans_split_kernel(
    const float* __restrict__ V, __nv_bfloat16* __restrict__ Th,
    __nv_bfloat16* __restrict__ Tl)
{
    __shared__ float t[32][33];
    const int k0 = blockIdx.x * 32, d0 = blockIdx.y * 32;
    const int bh = blockIdx.z;
    const int b = bh >> 4, h = bh & 15;
    int tx = threadIdx.x, ty = threadIdx.y;
    #pragma unroll
    for (int j = 0; j < 32; j += 8)
        t[ty + j][tx] = V[(size_t)(b * NSEQ + k0 + ty + j) * D_IN + h * HDIM + d0 + tx];
    __syncthreads();
    #pragma unroll
    for (int j = 0; j < 32; j += 8) {
        float v = t[tx][ty + j];
        __nv_bfloat16 hb = __float2bfloat16(v);
        size_t o = (size_t)(bh * HDIM + d0 + ty + j) * NSEQ + k0 + tx;
        Th[o] = hb;
        Tl[o] = __float2bfloat16(v - __bfloat162float(hb));
    }
}

// ---------------------------------------------------------------------------
// Pipelined split-bf16 GEMM, ldmatrix fragments, cp.async double buffering.
// MODE 0: C = A@Bt + bias (fp32 out).  MODE 2: fused QKV epilogue routing.
// ---------------------------------------------------------------------------
#define BK2 32
#define AS2 40
#define MAT_E (128 * AS2)
#define STG_E (4 * MAT_E)
#define GSMEM (2 * STG_E * 2)

template<int MODE>
__global__ __launch_bounds__(256, 2) void gemm_ld_kernel(
    const __nv_bfloat16* __restrict__ Ah_, const __nv_bfloat16* __restrict__ Al_,
    const __nv_bfloat16* __restrict__ Bh_, const __nv_bfloat16* __restrict__ Bl_,
    const float* __restrict__ bias, float* __restrict__ C,
    __nv_bfloat16* __restrict__ oQh, __nv_bfloat16* __restrict__ oQl,
    __nv_bfloat16* __restrict__ oKh, __nv_bfloat16* __restrict__ oKl,
    float* __restrict__ oV)
{
    extern __shared__ __nv_bfloat16 smem[];
    const int tid = threadIdx.x;
    const int wid = tid >> 5, lane = tid & 31;
    const int g = lane >> 2, tig = lane & 3;
    const int warpRow = (wid >> 1) * 32;
    const int warpCol = (wid & 1) * 64;
    const int rowBase = blockIdx.y * 128;
    const int colBase = blockIdx.x * 128;

    const __nv_bfloat16* gA0 = Ah_ + (size_t)rowBase * GK;
    const __nv_bfloat16* gA1 = Al_ + (size_t)rowBase * GK;
    const __nv_bfloat16* gB0 = Bh_ + (size_t)colBase * GK;
    const __nv_bfloat16* gB1 = Bl_ + (size_t)colBase * GK;

    float acc[2][8][4];
    #pragma unroll
    for (int mt = 0; mt < 2; mt++)
        #pragma unroll
        for (int nt = 0; nt < 8; nt++)
            #pragma unroll
            for (int j = 0; j < 4; j++) acc[mt][nt][j] = 0.f;

    const int lr = tid >> 1, lh = tid & 1;
    const uint32_t sbase = smem_u32(smem);
    const size_t gbase = (size_t)lr * GK + lh * 16;
    const uint32_t sb0 = sbase + (lr * AS2 + lh * 16) * 2;

    // ldmatrix per-lane addressing
    const int frow = (lane & 7) + ((lane >> 3) & 1) * 8;
    const int fcol = (lane >> 4) * 8;

    const int NIT = GK / BK2;  // 32

    {
        #pragma unroll
        for (int c = 0; c < 2; c++) {
            cp16(sb0 + c * 16 + 0 * MAT_E * 2, gA0 + gbase + c * 8);
            cp16(sb0 + c * 16 + 1 * MAT_E * 2, gA1 + gbase + c * 8);
            cp16(sb0 + c * 16 + 2 * MAT_E * 2, gB0 + gbase + c * 8);
            cp16(sb0 + c * 16 + 3 * MAT_E * 2, gB1 + gbase + c * 8);
        }
        asm volatile("cp.async.commit_group;" ::: "memory");
    }

    for (int it = 0; it < NIT; it++) {
        if (it + 1 < NIT) {
            const int k0 = (it + 1) * BK2;
            const uint32_t sb = sb0 + ((it + 1) & 1) * STG_E * 2;
            #pragma unroll
            for (int c = 0; c < 2; c++) {
                cp16(sb + c * 16 + 0 * MAT_E * 2, gA0 + gbase + k0 + c * 8);
                cp16(sb + c * 16 + 1 * MAT_E * 2, gA1 + gbase + k0 + c * 8);
                cp16(sb + c * 16 + 2 * MAT_E * 2, gB0 + gbase + k0 + c * 8);
                cp16(sb + c * 16 + 3 * MAT_E * 2, gB1 + gbase + k0 + c * 8);
            }
            asm volatile("cp.async.commit_group;" ::: "memory");
            asm volatile("cp.async.wait_group 1;" ::: "memory");
        } else {
            asm volatile("cp.async.wait_group 0;" ::: "memory");
        }
        __syncthreads();

        const uint32_t stg = sbase + (it & 1) * STG_E * 2;

        #pragma unroll
        for (int ks = 0; ks < 2; ks++) {
            const uint32_t cb = (uint32_t)(ks * 16 + fcol) * 2;
            uint32_t ah[2][4], al[2][4];
            #pragma unroll
            for (int mt = 0; mt < 2; mt++) {
                const uint32_t rb = (uint32_t)(warpRow + mt * 16 + frow) * (AS2 * 2);
                ldsm4(ah[mt], stg + 0 * MAT_E * 2 + rb + cb);
                ldsm4(al[mt], stg + 1 * MAT_E * 2 + rb + cb);
            }
            #pragma unroll
            for (int ntp = 0; ntp < 4; ntp++) {
                const uint32_t rb = (uint32_t)(warpCol + ntp * 16 + frow) * (AS2 * 2);
                uint32_t bh4[4], bl4[4];
                ldsm4(bh4, stg + 2 * MAT_E * 2 + rb + cb);
                ldsm4(bl4, stg + 3 * MAT_E * 2 + rb + cb);
                #pragma unroll
                for (int s = 0; s < 2; s++) {
                    const int nt = ntp * 2 + s;
                    #pragma unroll
                    for (int mt = 0; mt < 2; mt++) {
                        mma_bf16(acc[mt][nt], ah[mt], bh4[s], bh4[2 + s]);
                        mma_bf16(acc[mt][nt], ah[mt], bl4[s], bl4[2 + s]);
                        mma_bf16(acc[mt][nt], al[mt], bh4[s], bh4[2 + s]);
                    }
                }
            }
        }
        __syncthreads();
    }

    // epilogue
    #pragma unroll
    for (int mt = 0; mt < 2; mt++) {
        #pragma unroll
        for (int nt = 0; nt < 8; nt++) {
            const int r0 = rowBase + warpRow + mt * 16 + g;
            if (MODE == 0) {
                const int col = colBase + warpCol + nt * 8 + tig * 2;
                float bx = bias ? bias[col] : 0.f;
                float by = bias ? bias[col + 1] : 0.f;
                float2 v0 = {acc[mt][nt][0] + bx, acc[mt][nt][1] + by};
                float2 v1 = {acc[mt][nt][2] + bx, acc[mt][nt][3] + by};
                *(float2*)(C + (size_t)r0 * D_IN + col) = v0;
                *(float2*)(C + (size_t)(r0 + 8) * D_IN + col) = v1;
            } else {
                const int region = colBase >> 10;                      // 0:Q 1:K 2:V
                const int col = (colBase & 1023) + warpCol + nt * 8 + tig * 2;
                float2 v0 = {acc[mt][nt][0], acc[mt][nt][1]};
                float2 v1 = {acc[mt][nt][2], acc[mt][nt][3]};
                if (region == 2) {
                    *(float2*)(oV + (size_t)r0 * D_IN + col) = v0;
                    *(float2*)(oV + (size_t)(r0 + 8) * D_IN + col) = v1;
                } else {
                    __nv_bfloat16* Ho = (region == 0) ? oQh : oKh;
                    __nv_bfloat16* Lo = (region == 0) ? oQl : oKl;
                    __nv_bfloat162 h0 = __float22bfloat162_rn(v0);
                    __nv_bfloat162 h1 = __float22bfloat162_rn(v1);
                    __nv_bfloat162 l0 = __float22bfloat162_rn(make_float2(
                        v0.x - __bfloat162float(h0.x), v0.y - __bfloat162float(h0.y)));
                    __nv_bfloat162 l1 = __float22bfloat162_rn(make_float2(
                        v1.x - __bfloat162float(h1.x), v1.y - __bfloat162float(h1.y)));
                    *(uint32_t*)(Ho + (size_t)r0 * D_IN + col) = *(uint32_t*)&h0;
                    *(uint32_t*)(Ho + (size_t)(r0 + 8) * D_IN + col) = *(uint32_t*)&h1;
                    *(uint32_t*)(Lo + (size_t)r0 * D_IN + col) = *(uint32_t*)&l0;
                    *(uint32_t*)(Lo + (size_t)(r0 + 8) * D_IN + col) = *(uint32_t*)&l1;
                }
            }
        }
    }
}

// ---------------------------------------------------------------------------
// Tensor-core causal flash attention (unchanged from R6)
// ---------------------------------------------------------------------------
#define KSTR 72
#define EXP_C 0.1803368801111204f   // log2(e)/8

__global__ __launch_bounds__(256) void attn_mma_kernel(
    const __nv_bfloat16* __restrict__ Qh, const __nv_bfloat16* __restrict__ Ql,
    const __nv_bfloat16* __restrict__ Kh, const __nv_bfloat16* __restrict__ Kl,
    const __nv_bfloat16* __restrict__ Vth, const __nv_bfloat16* __restrict__ Vtl,
    __nv_bfloat16* __restrict__ Ch, __nv_bfloat16* __restrict__ Cl)
{
    __shared__ __nv_bfloat16 sKh[64 * KSTR];
    __shared__ __nv_bfloat16 sKl[64 * KSTR];
    __shared__ __nv_bfloat16 sVh[64 * KSTR];
    __shared__ __nv_bfloat16 sVl[64 * KSTR];

    const int tid = threadIdx.x;
    const int wid = tid >> 5, lane = tid & 31;
    const int g = lane >> 2, tig = lane & 3;
    const int q0 = blockIdx.x * 128;
    const int h = blockIdx.y, b = blockIdx.z;
    const int bh = b * NHEAD + h;
    const int rA = q0 + wid * 16 + g;
    const int rB = rA + 8;

    const size_t qrow = (size_t)(b * NSEQ + q0 + wid * 16) * D_IN + h * HDIM;
    uint32_t qh[4][4], ql[4][4];
    #pragma unroll
    for (int ks = 0; ks < 4; ks++) {
        const int col = ks * 16 + tig * 2;
        qh[ks][0] = *(const uint32_t*)(Qh + qrow + (size_t)g * D_IN + col);
        qh[ks][1] = *(const uint32_t*)(Qh + qrow + (size_t)(g + 8) * D_IN + col);
        qh[ks][2] = *(const uint32_t*)(Qh + qrow + (size_t)g * D_IN + col + 8);
        qh[ks][3] = *(const uint32_t*)(Qh + qrow + (size_t)(g + 8) * D_IN + col + 8);
        ql[ks][0] = *(const uint32_t*)(Ql + qrow + (size_t)g * D_IN + col);
        ql[ks][1] = *(const uint32_t*)(Ql + qrow + (size_t)(g + 8) * D_IN + col);
        ql[ks][2] = *(const uint32_t*)(Ql + qrow + (size_t)g * D_IN + col + 8);
        ql[ks][3] = *(const uint32_t*)(Ql + qrow + (size_t)(g + 8) * D_IN + col + 8);
    }

    float O[8][4];
    #pragma unroll
    for (int nt = 0; nt < 8; nt++)
        #pragma unroll
        for (int j = 0; j < 4; j++) O[nt][j] = 0.f;
    float la = 0.f, lb = 0.f;

    const int ktmax = (q0 + 127) >> 6;
    const int lr = tid >> 3, lc = (tid & 7) * 8;

    for (int kt = 0; kt <= ktmax; kt++) {
        const int k0 = kt * 64;
        __syncthreads();
        #pragma unroll
        for (int i = 0; i < 2; i++) {
            const int r = lr + i * 32;
            const size_t gk = (size_t)(b * NSEQ + k0 + r) * D_IN + h * HDIM + lc;
            const size_t gv = (size_t)(bh * HDIM + r) * NSEQ + k0 + lc;
            *(uint4*)(sKh + r * KSTR + lc) = *(const uint4*)(Kh + gk);
            *(uint4*)(sKl + r * KSTR + lc) = *(const uint4*)(Kl + gk);
            *(uint4*)(sVh + r * KSTR + lc) = *(const uint4*)(Vth + gv);
            *(uint4*)(sVl + r * KSTR + lc) = *(const uint4*)(Vtl + gv);
        }
        __syncthreads();

        if (k0 > q0 + wid * 16 + 15) continue;

        float S[8][4];
        #pragma unroll
        for (int nt = 0; nt < 8; nt++)
            #pragma unroll
            for (int j = 0; j < 4; j++) S[nt][j] = 0.f;

        #pragma unroll
        for (int ks = 0; ks < 4; ks++) {
            const int koff = ks * 16 + tig * 2;
            #pragma unroll
            for (int nt = 0; nt < 8; nt++) {
                const int n = nt * 8 + g;
                uint32_t b0h = *(const uint32_t*)(sKh + n * KSTR + koff);
                uint32_t b1h = *(const uint32_t*)(sKh + n * KSTR + koff + 8);
                uint32_t b0l = *(const uint32_t*)(sKl + n * KSTR + koff);
                uint32_t b1l = *(const uint32_t*)(sKl + n * KSTR + koff + 8);
                mma_bf16(S[nt], qh[ks], b0h, b1h);
                mma_bf16(S[nt], qh[ks], b0l, b1l);
                mma_bf16(S[nt], ql[ks], b0h, b1h);
            }
        }

        uint32_t ph[4][4], pl[4][4];
        #pragma unroll
        for (int nt = 0; nt < 8; nt++) {
            const int c0 = k0 + nt * 8 + tig * 2;
            const int c1 = c0 + 1;
            float p0 = (c0 <= rA) ? fexp2(S[nt][0] * EXP_C) : 0.f;
            float p1 = (c1 <= rA) ? fexp2(S[nt][1] * EXP_C) : 0.f;
            float p2 = (c0 <= rB) ? fexp2(S[nt][2] * EXP_C) : 0.f;
            float p3 = (c1 <= rB) ? fexp2(S[nt][3] * EXP_C) : 0.f;
            la += p0 + p1;
            lb += p2 + p3;
            __nv_bfloat162 h01 = __float22bfloat162_rn(make_float2(p0, p1));
            __nv_bfloat162 h23 = __float22bfloat162_rn(make_float2(p2, p3));
            __nv_bfloat162 l01 = __float22bfloat162_rn(make_float2(
                p0 - __bfloat162float(h01.x), p1 - __bfloat162float(h01.y)));
            __nv_bfloat162 l23 = __float22bfloat162_rn(make_float2(
                p2 - __bfloat162float(h23.x), p3 - __bfloat162float(h23.y)));
            const int ks = nt >> 1, half = (nt & 1) * 2;
            ph[ks][half + 0] = *(uint32_t*)&h01;
            ph[ks][half + 1] = *(uint32_t*)&h23;
            pl[ks][half + 0] = *(uint32_t*)&l01;
            pl[ks][half + 1] = *(uint32_t*)&l23;
        }

        #pragma unroll
        for (int ks = 0; ks < 4; ks++) {
            const int koff = ks * 16 + tig * 2;
            #pragma unroll
            for (int nt = 0; nt < 8; nt++) {
                const int n = nt * 8 + g;
                uint32_t b0h = *(const uint32_t*)(sVh + n * KSTR + koff);
                uint32_t b1h = *(const uint32_t*)(sVh + n * KSTR + koff + 8);
                uint32_t b0l = *(const uint32_t*)(sVl + n * KSTR + koff);
                uint32_t b1l = *(const uint32_t*)(sVl + n * KSTR + koff + 8);
                mma_bf16(O[nt], ph[ks], b0h, b1h);
                mma_bf16(O[nt], ph[ks], b0l, b1l);
                mma_bf16(O[nt], pl[ks], b0h, b1h);
            }
        }
    }

    la += __shfl_xor_sync(0xFFFFFFFF, la, 1);
    la += __shfl_xor_sync(0xFFFFFFFF, la, 2);
    lb += __shfl_xor_sync(0xFFFFFFFF, lb, 1);
    lb += __shfl_xor_sync(0xFFFFFFFF, lb, 2);
    const float ia = 1.f / la, ib = 1.f / lb;

    #pragma unroll
    for (int nt = 0; nt < 8; nt++) {
        const int col = h * HDIM + nt * 8 + tig * 2;
        float2 vA = {O[nt][0] * ia, O[nt][1] * ia};
        float2 vB = {O[nt][2] * ib, O[nt][3] * ib};
        __nv_bfloat162 hA = __float22bfloat162_rn(vA);
        __nv_bfloat162 hB = __float22bfloat162_rn(vB);
        __nv_bfloat162 lA = __float22bfloat162_rn(make_float2(
            vA.x - __bfloat162float(hA.x), vA.y - __bfloat162float(hA.y)));
        __nv_bfloat162 lB = __float22bfloat162_rn(make_float2(
            vB.x - __bfloat162float(hB.x), vB.y - __bfloat162float(hB.y)));
        *(uint32_t*)(Ch + (size_t)(b * NSEQ + rA) * D_IN + col) = *(uint32_t*)&hA;
        *(uint32_t*)(Ch + (size_t)(b * NSEQ + rB) * D_IN + col) = *(uint32_t*)&hB;
        *(uint32_t*)(Cl + (size_t)(b * NSEQ + rA) * D_IN + col) = *(uint32_t*)&lA;
        *(uint32_t*)(Cl + (size_t)(b * NSEQ + rB) * D_IN + col) = *(uint32_t*)&lB;
    }
}

// ---------------------------------------------------------------------------
extern "C" void kernel_launch(void* const* d_in, const int* in_sizes, int n_in,
                              void* d_out, int out_size)
{
    const float* X  = (const float*)d_in[0];
    const float* Wq = (const float*)d_in[1];
    const float* Wk = (const float*)d_in[2];
    const float* Wv = (const float*)d_in[3];
    const float* Wo = (const float*)d_in[4];
    const float* bo = (const float*)d_in[5];
    float* out = (float*)d_out;

    float* pV;
    __nv_bfloat16 *pXh, *pXl, *pCh, *pCl, *pWth, *pWtl;
    __nv_bfloat16 *pQh, *pQl, *pKh, *pKl, *pVth, *pVtl;
    cudaGetSymbolAddress((void**)&pV, g_V);
    cudaGetSymbolAddress((void**)&pXh, g_Xh);
    cudaGetSymbolAddress((void**)&pXl, g_Xl);
    cudaGetSymbolAddress((void**)&pCh, g_Ch);
    cudaGetSymbolAddress((void**)&pCl, g_Cl);
    cudaGetSymbolAddress((void**)&pWth, g_Wth);
    cudaGetSymbolAddress((void**)&pWtl, g_Wtl);
    cudaGetSymbolAddress((void**)&pQh, g_Qh);
    cudaGetSymbolAddress((void**)&pQl, g_Ql);
    cudaGetSymbolAddress((void**)&pKh, g_Kh);
    cudaGetSymbolAddress((void**)&pKl, g_Kl);
    cudaGetSymbolAddress((void**)&pVth, g_Vth);
    cudaGetSymbolAddress((void**)&pVtl, g_Vtl);

    static bool attrs_set = false;
    if (!attrs_set) {
        cudaFuncSetAttribute(gemm_ld_kernel<0>,
                             cudaFuncAttributeMaxDynamicSharedMemorySize, GSMEM);
        cudaFuncSetAttribute(gemm_ld_kernel<2>,
                             cudaFuncAttributeMaxDynamicSharedMemorySize, GSMEM);
        attrs_set = true;
    }

    const int splitBlocks = (MTOT * D_IN) / (256 * 4);
    const dim3 trGrid(D_IN / 32, D_IN / 32), trBlk(32, 8);
    const dim3 vtGrid(NSEQ / 32, HDIM / 32, BATCH * NHEAD);

    split_kernel<<<splitBlocks, 256>>>(X, pXh, pXl);

    transpose_split_kernel<<<trGrid, trBlk>>>(Wq, pWth, pWtl, 0);
    transpose_split_kernel<<<trGrid, trBlk>>>(Wk, pWth, pWtl, 1024);
    transpose_split_kernel<<<trGrid, trBlk>>>(Wv, pWth, pWtl, 2048);

    gemm_ld_kernel<2><<<dim3(NQKV / 128, MTOT / 128), 256, GSMEM>>>(
        pXh, pXl, pWth, pWtl, nullptr, nullptr, pQh, pQl, pKh, pKl, pV);

    vtrans_split_kernel<<<vtGrid, trBlk>>>(pV, pVth, pVtl);

    attn_mma_kernel<<<dim3(NSEQ / 128, NHEAD, BATCH), 256>>>(
        pQh, pQl, pKh, pKl, pVth, pVtl, pCh, pCl);

    transpose_split_kernel<<<trGrid, trBlk>>>(Wo, pWth, pWtl, 0);
    gemm_ld_kernel<0><<<dim3(D_IN / 128, MTOT / 128), 256, GSMEM>>>(
        pCh, pCl, pWth, pWtl, bo, out, nullptr, nullptr, nullptr, nullptr, nullptr);
}

// round 8
// speedup vs baseline: 3.0206x; 1.0320x over previous
#include <cuda_runtime.h>
#include <cuda_bf16.h>
#include <cstdint>

// Problem constants
#define D_IN   1024
#define NSEQ   2048
#define BATCH  4
#define NHEAD  16
#define HDIM   64
#define MTOT   (BATCH*NSEQ)   // 8192
#define GK     1024
#define NQKV   3072

// ---------------------------------------------------------------------------
// Scratch (no cudaMalloc allowed)
// ---------------------------------------------------------------------------
__device__ __nv_bfloat16 g_Xh[(size_t)MTOT * D_IN];
__device__ __nv_bfloat16 g_Xl[(size_t)MTOT * D_IN];
__device__ __nv_bfloat16 g_Ch[(size_t)MTOT * D_IN];
__device__ __nv_bfloat16 g_Cl[(size_t)MTOT * D_IN];
__device__ __nv_bfloat16 g_Wth[(size_t)NQKV * D_IN];
__device__ __nv_bfloat16 g_Wtl[(size_t)NQKV * D_IN];
__device__ __nv_bfloat16 g_Qh[(size_t)MTOT * D_IN];
__device__ __nv_bfloat16 g_Ql[(size_t)MTOT * D_IN];
__device__ __nv_bfloat16 g_Kh[(size_t)MTOT * D_IN];
__device__ __nv_bfloat16 g_Kl[(size_t)MTOT * D_IN];
__device__ __nv_bfloat16 g_Vth[(size_t)BATCH * NHEAD * HDIM * NSEQ];
__device__ __nv_bfloat16 g_Vtl[(size_t)BATCH * NHEAD * HDIM * NSEQ];

__device__ __forceinline__ float fexp2(float x) {
    float r;
    asm("ex2.approx.f32 %0, %1;" : "=f"(r) : "f"(x));
    return r;
}
__device__ __forceinline__ uint32_t smem_u32(const void* p) {
    uint32_t a;
    asm("{ .reg .u64 t; cvta.to.shared.u64 t, %1; cvt.u32.u64 %0, t; }" : "=r"(a) : "l"(p));
    return a;
}
__device__ __forceinline__ void cp16(uint32_t saddr, const void* gptr) {
    asm volatile("cp.async.cg.shared.global [%0], [%1], 16;" :: "r"(saddr), "l"(gptr));
}
__device__ __forceinline__ void ldsm4(uint32_t* r, uint32_t saddr) {
    asm volatile("ldmatrix.sync.aligned.m8n8.x4.shared.b16 {%0,%1,%2,%3}, [%4];"
        : "=r"(r[0]), "=r"(r[1]), "=r"(r[2]), "=r"(r[3]) : "r"(saddr));
}
__device__ __forceinline__ void mma_bf16(float* c, const uint32_t* a,
                                         uint32_t b0, uint32_t b1)
{
    asm volatile(
        "mma.sync.aligned.m16n8k16.row.col.f32.bf16.bf16.f32 "
        "{%0,%1,%2,%3}, {%4,%5,%6,%7}, {%8,%9}, {%0,%1,%2,%3};"
        : "+f"(c[0]), "+f"(c[1]), "+f"(c[2]), "+f"(c[3])
        : "r"(a[0]), "r"(a[1]), "r"(a[2]), "r"(a[3]), "r"(b0), "r"(b1));
}

// ---------------------------------------------------------------------------
// Split fp32 -> bf16 hi + lo (used only for X)
// ---------------------------------------------------------------------------
__global__ __launch_bounds__(256) void split_kernel(
    const float* __restrict__ x, __nv_bfloat16* __restrict__ hi,
    __nv_bfloat16* __restrict__ lo)
{
    size_t i = (size_t)blockIdx.x * 256 + threadIdx.x;
    float4 v = ((const float4*)x)[i];
    __nv_bfloat16 h0 = __float2bfloat16(v.x), h1 = __float2bfloat16(v.y);
    __nv_bfloat16 h2 = __float2bfloat16(v.z), h3 = __float2bfloat16(v.w);
    __nv_bfloat16 l0 = __float2bfloat16(v.x - __bfloat162float(h0));
    __nv_bfloat16 l1 = __float2bfloat16(v.y - __bfloat162float(h1));
    __nv_bfloat16 l2 = __float2bfloat16(v.z - __bfloat162float(h2));
    __nv_bfloat16 l3 = __float2bfloat16(v.w - __bfloat162float(h3));
    __nv_bfloat162 hv0{h0, h1}, hv1{h2, h3}, lv0{l0, l1}, lv1{l2, l3};
    ((__nv_bfloat162*)hi)[i * 2 + 0] = hv0;
    ((__nv_bfloat162*)hi)[i * 2 + 1] = hv1;
    ((__nv_bfloat162*)lo)[i * 2 + 0] = lv0;
    ((__nv_bfloat162*)lo)[i * 2 + 1] = lv1;
}

// ---------------------------------------------------------------------------
// Transpose + split weights: W[K,1024] fp32 -> Wt[rowOff+N][K] bf16 hi/lo
// ---------------------------------------------------------------------------
__global__ __launch_bounds__(256) void transpose_split_kernel(
    const float* __restrict__ W, __nv_bfloat16* __restrict__ Th,
    __nv_bfloat16* __restrict__ Tl, int rowOff)
{
    __shared__ float t[32][33];
    int x0 = blockIdx.x * 32, y0 = blockIdx.y * 32;
    int tx = threadIdx.x, ty = threadIdx.y;  // (32, 8)
    #pragma unroll
    for (int j = 0; j < 32; j += 8)
        t[ty + j][tx] = W[(size_t)(y0 + ty + j) * D_IN + x0 + tx];
    __syncthreads();
    #pragma unroll
    for (int j = 0; j < 32; j += 8) {
        float v = t[tx][ty + j];
        __nv_bfloat16 h = __float2bfloat16(v);
        size_t o = (size_t)(rowOff + x0 + ty + j) * GK + y0 + tx;
        Th[o] = h;
        Tl[o] = __float2bfloat16(v - __bfloat162float(h));
    }
}

// ---------------------------------------------------------------------------
// Pipelined split-bf16 GEMM, ldmatrix fragments, cp.async double buffering.
// MODE 0: C = A@Bt + bias (fp32 out).
// MODE 2: fused QKV; V region writes transposed split Vt via smem staging.
// ---------------------------------------------------------------------------
#define BK2 32
#define AS2 40
#define MAT_E (128 * AS2)
#define STG_E (4 * MAT_E)
#define GSMEM (2 * STG_E * 2)     // 81920 bytes
#define VT_STR 136                 // transposed stage row stride (elems)

template<int MODE>
__global__ __launch_bounds__(256, 2) void gemm_ld_kernel(
    const __nv_bfloat16* __restrict__ Ah_, const __nv_bfloat16* __restrict__ Al_,
    const __nv_bfloat16* __restrict__ Bh_, const __nv_bfloat16* __restrict__ Bl_,
    const float* __restrict__ bias, float* __restrict__ C,
    __nv_bfloat16* __restrict__ oQh, __nv_bfloat16* __restrict__ oQl,
    __nv_bfloat16* __restrict__ oKh, __nv_bfloat16* __restrict__ oKl,
    __nv_bfloat16* __restrict__ oVth, __nv_bfloat16* __restrict__ oVtl)
{
    extern __shared__ __nv_bfloat16 smem[];
    const int tid = threadIdx.x;
    const int wid = tid >> 5, lane = tid & 31;
    const int g = lane >> 2, tig = lane & 3;
    const int warpRow = (wid >> 1) * 32;
    const int warpCol = (wid & 1) * 64;
    const int rowBase = blockIdx.y * 128;
    const int colBase = blockIdx.x * 128;

    const __nv_bfloat16* gA0 = Ah_ + (size_t)rowBase * GK;
    const __nv_bfloat16* gA1 = Al_ + (size_t)rowBase * GK;
    const __nv_bfloat16* gB0 = Bh_ + (size_t)colBase * GK;
    const __nv_bfloat16* gB1 = Bl_ + (size_t)colBase * GK;

    float acc[2][8][4];
    #pragma unroll
    for (int mt = 0; mt < 2; mt++)
        #pragma unroll
        for (int nt = 0; nt < 8; nt++)
            #pragma unroll
            for (int j = 0; j < 4; j++) acc[mt][nt][j] = 0.f;

    const int lr = tid >> 1, lh = tid & 1;
    const uint32_t sbase = smem_u32(smem);
    const size_t gbase = (size_t)lr * GK + lh * 16;
    const uint32_t sb0 = sbase + (lr * AS2 + lh * 16) * 2;

    const int frow = (lane & 7) + ((lane >> 3) & 1) * 8;
    const int fcol = (lane >> 4) * 8;

    const int NIT = GK / BK2;  // 32

    {
        #pragma unroll
        for (int c = 0; c < 2; c++) {
            cp16(sb0 + c * 16 + 0 * MAT_E * 2, gA0 + gbase + c * 8);
            cp16(sb0 + c * 16 + 1 * MAT_E * 2, gA1 + gbase + c * 8);
            cp16(sb0 + c * 16 + 2 * MAT_E * 2, gB0 + gbase + c * 8);
            cp16(sb0 + c * 16 + 3 * MAT_E * 2, gB1 + gbase + c * 8);
        }
        asm volatile("cp.async.commit_group;" ::: "memory");
    }

    for (int it = 0; it < NIT; it++) {
        if (it + 1 < NIT) {
            const int k0 = (it + 1) * BK2;
            const uint32_t sb = sb0 + ((it + 1) & 1) * STG_E * 2;
            #pragma unroll
            for (int c = 0; c < 2; c++) {
                cp16(sb + c * 16 + 0 * MAT_E * 2, gA0 + gbase + k0 + c * 8);
                cp16(sb + c * 16 + 1 * MAT_E * 2, gA1 + gbase + k0 + c * 8);
                cp16(sb + c * 16 + 2 * MAT_E * 2, gB0 + gbase + k0 + c * 8);
                cp16(sb + c * 16 + 3 * MAT_E * 2, gB1 + gbase + k0 + c * 8);
            }
            asm volatile("cp.async.commit_group;" ::: "memory");
            asm volatile("cp.async.wait_group 1;" ::: "memory");
        } else {
            asm volatile("cp.async.wait_group 0;" ::: "memory");
        }
        __syncthreads();

        const uint32_t stg = sbase + (it & 1) * STG_E * 2;

        #pragma unroll
        for (int ks = 0; ks < 2; ks++) {
            const uint32_t cb = (uint32_t)(ks * 16 + fcol) * 2;
            uint32_t ah[2][4], al[2][4];
            #pragma unroll
            for (int mt = 0; mt < 2; mt++) {
                const uint32_t rb = (uint32_t)(warpRow + mt * 16 + frow) * (AS2 * 2);
                ldsm4(ah[mt], stg + 0 * MAT_E * 2 + rb + cb);
                ldsm4(al[mt], stg + 1 * MAT_E * 2 + rb + cb);
            }
            #pragma unroll
            for (int ntp = 0; ntp < 4; ntp++) {
                const uint32_t rb = (uint32_t)(warpCol + ntp * 16 + frow) * (AS2 * 2);
                uint32_t bh4[4], bl4[4];
                ldsm4(bh4, stg + 2 * MAT_E * 2 + rb + cb);
                ldsm4(bl4, stg + 3 * MAT_E * 2 + rb + cb);
                #pragma unroll
                for (int s = 0; s < 2; s++) {
                    const int nt = ntp * 2 + s;
                    #pragma unroll
                    for (int mt = 0; mt < 2; mt++) {
                        mma_bf16(acc[mt][nt], ah[mt], bh4[s], bh4[2 + s]);
                        mma_bf16(acc[mt][nt], ah[mt], bl4[s], bl4[2 + s]);
                        mma_bf16(acc[mt][nt], al[mt], bh4[s], bh4[2 + s]);
                    }
                }
            }
        }
        __syncthreads();
    }

    // ---------------- epilogue ----------------
    const int region = (MODE == 2) ? (colBase >> 10) : 0;   // 0:Q 1:K 2:V

    if (MODE == 2 && region == 2) {
        // V: transpose+split through smem, write Vt[(b*16+h)*64+d][seq] hi/lo
        __nv_bfloat16* tH = smem;                 // [128][VT_STR]
        __nv_bfloat16* tL = smem + 128 * VT_STR;
        #pragma unroll
        for (int mt = 0; mt < 2; mt++) {
            #pragma unroll
            for (int nt = 0; nt < 8; nt++) {
                const int cl = warpCol + nt * 8 + tig * 2;
                const int rl = warpRow + mt * 16 + g;
                #pragma unroll
                for (int j = 0; j < 4; j++) {
                    const int c = cl + (j & 1);
                    const int r = rl + (j >> 1) * 8;
                    float v = acc[mt][nt][j];
                    __nv_bfloat16 hb = __float2bfloat16(v);
                    tH[c * VT_STR + r] = hb;
                    tL[c * VT_STR + r] = __float2bfloat16(v - __bfloat162float(hb));
                }
            }
        }
        __syncthreads();
        const int dl = tid >> 1, hf = tid & 1;
        const int bq = rowBase / NSEQ;
        const int seq0 = rowBase & (NSEQ - 1);
        const int h0 = (colBase & 1023) >> 6;
        const size_t orow = ((size_t)(bq * NHEAD + h0) * HDIM + dl) * NSEQ + seq0 + hf * 64;
        const __nv_bfloat16* sH = tH + dl * VT_STR + hf * 64;
        const __nv_bfloat16* sL = tL + dl * VT_STR + hf * 64;
        #pragma unroll
        for (int u = 0; u < 8; u++) {
            *(uint4*)(oVth + orow + u * 8) = *(const uint4*)(sH + u * 8);
            *(uint4*)(oVtl + orow + u * 8) = *(const uint4*)(sL + u * 8);
        }
        return;
    }

    #pragma unroll
    for (int mt = 0; mt < 2; mt++) {
        #pragma unroll
        for (int nt = 0; nt < 8; nt++) {
            const int r0 = rowBase + warpRow + mt * 16 + g;
            if (MODE == 0) {
                const int col = colBase + warpCol + nt * 8 + tig * 2;
                float bx = bias ? bias[col] : 0.f;
                float by = bias ? bias[col + 1] : 0.f;
                float2 v0 = {acc[mt][nt][0] + bx, acc[mt][nt][1] + by};
                float2 v1 = {acc[mt][nt][2] + bx, acc[mt][nt][3] + by};
                *(float2*)(C + (size_t)r0 * D_IN + col) = v0;
                *(float2*)(C + (size_t)(r0 + 8) * D_IN + col) = v1;
            } else {
                const int col = (colBase & 1023) + warpCol + nt * 8 + tig * 2;
                __nv_bfloat16* Ho = (region == 0) ? oQh : oKh;
                __nv_bfloat16* Lo = (region == 0) ? oQl : oKl;
                float2 v0 = {acc[mt][nt][0], acc[mt][nt][1]};
                float2 v1 = {acc[mt][nt][2], acc[mt][nt][3]};
                __nv_bfloat162 h0 = __float22bfloat162_rn(v0);
                __nv_bfloat162 h1 = __float22bfloat162_rn(v1);
                __nv_bfloat162 l0 = __float22bfloat162_rn(make_float2(
                    v0.x - __bfloat162float(h0.x), v0.y - __bfloat162float(h0.y)));
                __nv_bfloat162 l1 = __float22bfloat162_rn(make_float2(
                    v1.x - __bfloat162float(h1.x), v1.y - __bfloat162float(h1.y)));
                *(uint32_t*)(Ho + (size_t)r0 * D_IN + col) = *(uint32_t*)&h0;
                *(uint32_t*)(Ho + (size_t)(r0 + 8) * D_IN + col) = *(uint32_t*)&h1;
                *(uint32_t*)(Lo + (size_t)r0 * D_IN + col) = *(uint32_t*)&l0;
                *(uint32_t*)(Lo + (size_t)(r0 + 8) * D_IN + col) = *(uint32_t*)&l1;
            }
        }
    }
}

// ---------------------------------------------------------------------------
// Tensor-core causal flash attention, cp.async double-buffered tiles,
// heavy-first CTA ordering. 256 threads, key tiles of 64.
// ---------------------------------------------------------------------------
#define KSTR 72
#define TILE_B2 (64 * KSTR * 2)          // 9216 bytes per tile
#define ASTAGE_B (4 * TILE_B2)           // 36864 bytes per stage
#define ATTN_SMEM2 (2 * ASTAGE_B)        // 73728 bytes
#define EXP_C 0.1803368801111204f        // log2(e)/8

__global__ __launch_bounds__(256) void attn_mma_kernel(
    const __nv_bfloat16* __restrict__ Qh, const __nv_bfloat16* __restrict__ Ql,
    const __nv_bfloat16* __restrict__ Kh, const __nv_bfloat16* __restrict__ Kl,
    const __nv_bfloat16* __restrict__ Vth, const __nv_bfloat16* __restrict__ Vtl,
    __nv_bfloat16* __restrict__ Ch, __nv_bfloat16* __restrict__ Cl)
{
    extern __shared__ __nv_bfloat16 asmem[];
    const uint32_t sb = smem_u32(asmem);

    const int tid = threadIdx.x;
    const int wid = tid >> 5, lane = tid & 31;
    const int g = lane >> 2, tig = lane & 3;
    const int q0 = ((int)gridDim.x - 1 - (int)blockIdx.x) * 128;   // heavy first
    const int h = blockIdx.y, b = blockIdx.z;
    const int bh = b * NHEAD + h;
    const int rA = q0 + wid * 16 + g;
    const int rB = rA + 8;

    const size_t qrow = (size_t)(b * NSEQ + q0 + wid * 16) * D_IN + h * HDIM;
    uint32_t qh[4][4], ql[4][4];
    #pragma unroll
    for (int ks = 0; ks < 4; ks++) {
        const int col = ks * 16 + tig * 2;
        qh[ks][0] = *(const uint32_t*)(Qh + qrow + (size_t)g * D_IN + col);
        qh[ks][1] = *(const uint32_t*)(Qh + qrow + (size_t)(g + 8) * D_IN + col);
        qh[ks][2] = *(const uint32_t*)(Qh + qrow + (size_t)g * D_IN + col + 8);
        qh[ks][3] = *(const uint32_t*)(Qh + qrow + (size_t)(g + 8) * D_IN + col + 8);
        ql[ks][0] = *(const uint32_t*)(Ql + qrow + (size_t)g * D_IN + col);
        ql[ks][1] = *(const uint32_t*)(Ql + qrow + (size_t)(g + 8) * D_IN + col);
        ql[ks][2] = *(const uint32_t*)(Ql + qrow + (size_t)g * D_IN + col + 8);
        ql[ks][3] = *(const uint32_t*)(Ql + qrow + (size_t)(g + 8) * D_IN + col + 8);
    }

    float O[8][4];
    #pragma unroll
    for (int nt = 0; nt < 8; nt++)
        #pragma unroll
        for (int j = 0; j < 4; j++) O[nt][j] = 0.f;
    float la = 0.f, lb = 0.f;

    const int ktmax = (q0 + 127) >> 6;
    const int lr = tid >> 3, lc = (tid & 7) * 8;

    // tile loader (cp.async)
    auto load_tile = [&](int kt, int stage) {
        const int k0 = kt * 64;
        const uint32_t st = sb + stage * ASTAGE_B;
        #pragma unroll
        for (int i = 0; i < 2; i++) {
            const int r = lr + i * 32;
            const size_t gk = (size_t)(b * NSEQ + k0 + r) * D_IN + h * HDIM + lc;
            const size_t gv = (size_t)(bh * HDIM + r) * NSEQ + k0 + lc;
            const uint32_t so = (uint32_t)(r * KSTR + lc) * 2;
            cp16(st + 0 * TILE_B2 + so, Kh + gk);
            cp16(st + 1 * TILE_B2 + so, Kl + gk);
            cp16(st + 2 * TILE_B2 + so, Vth + gv);
            cp16(st + 3 * TILE_B2 + so, Vtl + gv);
        }
        asm volatile("cp.async.commit_group;" ::: "memory");
    };

    load_tile(0, 0);

    for (int kt = 0; kt <= ktmax; kt++) {
        if (kt < ktmax) {
            load_tile(kt + 1, (kt + 1) & 1);
            asm volatile("cp.async.wait_group 1;" ::: "memory");
        } else {
            asm volatile("cp.async.wait_group 0;" ::: "memory");
        }
        __syncthreads();

        const int k0 = kt * 64;
        const __nv_bfloat16* stg = asmem + (kt & 1) * (ASTAGE_B / 2);
        const __nv_bfloat16* sKh = stg;
        const __nv_bfloat16* sKl = stg + 64 * KSTR;
        const __nv_bfloat16* sVh = stg + 2 * 64 * KSTR;
        const __nv_bfloat16* sVl = stg + 3 * 64 * KSTR;

        if (k0 <= q0 + wid * 16 + 15) {
            float S[8][4];
            #pragma unroll
            for (int nt = 0; nt < 8; nt++)
                #pragma unroll
                for (int j = 0; j < 4; j++) S[nt][j] = 0.f;

            #pragma unroll
            for (int ks = 0; ks < 4; ks++) {
                const int koff = ks * 16 + tig * 2;
                #pragma unroll
                for (int nt = 0; nt < 8; nt++) {
                    const int n = nt * 8 + g;
                    uint32_t b0h = *(const uint32_t*)(sKh + n * KSTR + koff);
                    uint32_t b1h = *(const uint32_t*)(sKh + n * KSTR + koff + 8);
                    uint32_t b0l = *(const uint32_t*)(sKl + n * KSTR + koff);
                    uint32_t b1l = *(const uint32_t*)(sKl + n * KSTR + koff + 8);
                    mma_bf16(S[nt], qh[ks], b0h, b1h);
                    mma_bf16(S[nt], qh[ks], b0l, b1l);
                    mma_bf16(S[nt], ql[ks], b0h, b1h);
                }
            }

            uint32_t ph[4][4], pl[4][4];
            #pragma unroll
            for (int nt = 0; nt < 8; nt++) {
                const int c0 = k0 + nt * 8 + tig * 2;
                const int c1 = c0 + 1;
                float p0 = (c0 <= rA) ? fexp2(S[nt][0] * EXP_C) : 0.f;
                float p1 = (c1 <= rA) ? fexp2(S[nt][1] * EXP_C) : 0.f;
                float p2 = (c0 <= rB) ? fexp2(S[nt][2] * EXP_C) : 0.f;
                float p3 = (c1 <= rB) ? fexp2(S[nt][3] * EXP_C) : 0.f;
                la += p0 + p1;
                lb += p2 + p3;
                __nv_bfloat162 h01 = __float22bfloat162_rn(make_float2(p0, p1));
                __nv_bfloat162 h23 = __float22bfloat162_rn(make_float2(p2, p3));
                __nv_bfloat162 l01 = __float22bfloat162_rn(make_float2(
                    p0 - __bfloat162float(h01.x), p1 - __bfloat162float(h01.y)));
                __nv_bfloat162 l23 = __float22bfloat162_rn(make_float2(
                    p2 - __bfloat162float(h23.x), p3 - __bfloat162float(h23.y)));
                const int ks = nt >> 1, half = (nt & 1) * 2;
                ph[ks][half + 0] = *(uint32_t*)&h01;
                ph[ks][half + 1] = *(uint32_t*)&h23;
                pl[ks][half + 0] = *(uint32_t*)&l01;
                pl[ks][half + 1] = *(uint32_t*)&l23;
            }

            #pragma unroll
            for (int ks = 0; ks < 4; ks++) {
                const int koff = ks * 16 + tig * 2;
                #pragma unroll
                for (int nt = 0; nt < 8; nt++) {
                    const int n = nt * 8 + g;
                    uint32_t b0h = *(const uint32_t*)(sVh + n * KSTR + koff);
                    uint32_t b1h = *(const uint32_t*)(sVh + n * KSTR + koff + 8);
                    uint32_t b0l = *(const uint32_t*)(sVl + n * KSTR + koff);
                    uint32_t b1l = *(const uint32_t*)(sVl + n * KSTR + koff + 8);
                    mma_bf16(O[nt], ph[ks], b0h, b1h);
                    mma_bf16(O[nt], ph[ks], b0l, b1l);
                    mma_bf16(O[nt], pl[ks], b0h, b1h);
                }
            }
        }
        __syncthreads();   // protect stage from next prefetch overwrite
    }

    la += __shfl_xor_sync(0xFFFFFFFF, la, 1);
    la += __shfl_xor_sync(0xFFFFFFFF, la, 2);
    lb += __shfl_xor_sync(0xFFFFFFFF, lb, 1);
    lb += __shfl_xor_sync(0xFFFFFFFF, lb, 2);
    const float ia = 1.f / la, ib = 1.f / lb;

    #pragma unroll
    for (int nt = 0; nt < 8; nt++) {
        const int col = h * HDIM + nt * 8 + tig * 2;
        float2 vA = {O[nt][0] * ia, O[nt][1] * ia};
        float2 vB = {O[nt][2] * ib, O[nt][3] * ib};
        __nv_bfloat162 hA = __float22bfloat162_rn(vA);
        __nv_bfloat162 hB = __float22bfloat162_rn(vB);
        __nv_bfloat162 lA = __float22bfloat162_rn(make_float2(
            vA.x - __bfloat162float(hA.x), vA.y - __bfloat162float(hA.y)));
        __nv_bfloat162 lB = __float22bfloat162_rn(make_float2(
            vB.x - __bfloat162float(hB.x), vB.y - __bfloat162float(hB.y)));
        *(uint32_t*)(Ch + (size_t)(b * NSEQ + rA) * D_IN + col) = *(uint32_t*)&hA;
        *(uint32_t*)(Ch + (size_t)(b * NSEQ + rB) * D_IN + col) = *(uint32_t*)&hB;
        *(uint32_t*)(Cl + (size_t)(b * NSEQ + rA) * D_IN + col) = *(uint32_t*)&lA;
        *(uint32_t*)(Cl + (size_t)(b * NSEQ + rB) * D_IN + col) = *(uint32_t*)&lB;
    }
}

// ---------------------------------------------------------------------------
extern "C" void kernel_launch(void* const* d_in, const int* in_sizes, int n_in,
                              void* d_out, int out_size)
{
    const float* X  = (const float*)d_in[0];
    const float* Wq = (const float*)d_in[1];
    const float* Wk = (const float*)d_in[2];
    const float* Wv = (const float*)d_in[3];
    const float* Wo = (const float*)d_in[4];
    const float* bo = (const float*)d_in[5];
    float* out = (float*)d_out;

    __nv_bfloat16 *pXh, *pXl, *pCh, *pCl, *pWth, *pWtl;
    __nv_bfloat16 *pQh, *pQl, *pKh, *pKl, *pVth, *pVtl;
    cudaGetSymbolAddress((void**)&pXh, g_Xh);
    cudaGetSymbolAddress((void**)&pXl, g_Xl);
    cudaGetSymbolAddress((void**)&pCh, g_Ch);
    cudaGetSymbolAddress((void**)&pCl, g_Cl);
    cudaGetSymbolAddress((void**)&pWth, g_Wth);
    cudaGetSymbolAddress((void**)&pWtl, g_Wtl);
    cudaGetSymbolAddress((void**)&pQh, g_Qh);
    cudaGetSymbolAddress((void**)&pQl, g_Ql);
    cudaGetSymbolAddress((void**)&pKh, g_Kh);
    cudaGetSymbolAddress((void**)&pKl, g_Kl);
    cudaGetSymbolAddress((void**)&pVth, g_Vth);
    cudaGetSymbolAddress((void**)&pVtl, g_Vtl);

    static bool attrs_set = false;
    if (!attrs_set) {
        cudaFuncSetAttribute(gemm_ld_kernel<0>,
                             cudaFuncAttributeMaxDynamicSharedMemorySize, GSMEM);
        cudaFuncSetAttribute(gemm_ld_kernel<2>,
                             cudaFuncAttributeMaxDynamicSharedMemorySize, GSMEM);
        cudaFuncSetAttribute(attn_mma_kernel,
                             cudaFuncAttributeMaxDynamicSharedMemorySize, ATTN_SMEM2);
        attrs_set = true;
    }

    const int splitBlocks = (MTOT * D_IN) / (256 * 4);
    const dim3 trGrid(D_IN / 32, D_IN / 32), trBlk(32, 8);

    split_kernel<<<splitBlocks, 256>>>(X, pXh, pXl);

    transpose_split_kernel<<<trGrid, trBlk>>>(Wq, pWth, pWtl, 0);
    transpose_split_kernel<<<trGrid, trBlk>>>(Wk, pWth, pWtl, 1024);
    transpose_split_kernel<<<trGrid, trBlk>>>(Wv, pWth, pWtl, 2048);

    gemm_ld_kernel<2><<<dim3(NQKV / 128, MTOT / 128), 256, GSMEM>>>(
        pXh, pXl, pWth, pWtl, nullptr, nullptr,
        pQh, pQl, pKh, pKl, pVth, pVtl);

    attn_mma_kernel<<<dim3(NSEQ / 128, NHEAD, BATCH), 256, ATTN_SMEM2>>>(
        pQh, pQl, pKh, pKl, pVth, pVtl, pCh, pCl);

    transpose_split_kernel<<<trGrid, trBlk>>>(Wo, pWth, pWtl, 0);
    gemm_ld_kernel<0><<<dim3(D_IN / 128, MTOT / 128), 256, GSMEM>>>(
        pCh, pCl, pWth, pWtl, bo, out,
        nullptr, nullptr, nullptr, nullptr, nullptr, nullptr);
}